// round 14
// baseline (speedup 1.0000x reference)
#include <cuda_runtime.h>
#include <cuda_bf16.h>

// ConformerAttention: B=8, S=1024, D=512, H=8, hd=64, P=2047
// rel_shift identity: shifted[i,j] = raw[i, j + (S-1) - i] -> p row r = 1023 + j - i.
// 32-row q tiles: rlo = 992 - i0, j = rr + ii - 31.

#define CB 8
#define CS 1024
#define CD 512
#define CH 8
#define CHD 64
#define CP 2047
#define MTOK (CB*CS)   // 8192

typedef __nv_bfloat16 bf16;

__device__ __forceinline__ unsigned pack_bf2(float lo, float hi) {
    unsigned r; asm("cvt.rn.bf16x2.f32 %0, %1, %2;" : "=r"(r) : "f"(hi), "f"(lo)); return r;
}
__device__ __forceinline__ float bf_lo(unsigned u) { return __uint_as_float(u << 16); }
__device__ __forceinline__ float bf_hi(unsigned u) { return __uint_as_float(u & 0xFFFF0000u); }

__device__ __forceinline__ void mma16(float4& c, unsigned a0, unsigned a1, unsigned a2, unsigned a3,
                                      unsigned b0, unsigned b1) {
    asm volatile(
        "mma.sync.aligned.m16n8k16.row.col.f32.bf16.bf16.f32 "
        "{%0,%1,%2,%3}, {%4,%5,%6,%7}, {%8,%9}, {%0,%1,%2,%3};"
        : "+f"(c.x), "+f"(c.y), "+f"(c.z), "+f"(c.w)
        : "r"(a0), "r"(a1), "r"(a2), "r"(a3), "r"(b0), "r"(b1));
}
__device__ __forceinline__ unsigned sptr(const void* p) {
    return (unsigned)__cvta_generic_to_shared(p);
}
__device__ __forceinline__ void ldsm_x4(unsigned* r, unsigned addr) {
    asm volatile("ldmatrix.sync.aligned.m8n8.x4.shared.b16 {%0,%1,%2,%3}, [%4];"
        : "=r"(r[0]), "=r"(r[1]), "=r"(r[2]), "=r"(r[3]) : "r"(addr));
}

// -------- scratch (allocation-free: device globals) --------
__device__ bf16 g_h [MTOK*CD];
__device__ bf16 g_q [CB*CH*CS*CHD];      // [bh][S][hd]
__device__ bf16 g_k [CB*CH*CS*CHD];      // [bh][S][hd]
__device__ bf16 g_v [CB*CH*CS*CHD];      // [bh][hd][S]  (pre-transposed, mode 5)
__device__ bf16 g_p [CH*CP*CHD];         // [H][P][hd]
__device__ bf16 g_ao[MTOK*CD];           // [B,S,D]
__device__ bf16 g_wq[CD*CD], g_wk[CD*CD], g_wv[CD*CD], g_wo[CD*CD], g_wp[CD*CD];
__device__ bf16 g_pe[CP*CD];             // pos_emb bf16

// ============================ fused prep: weight/pe conversion + LayerNorm ============================
// blocks [0,640): wconv (5 x 128); [640,1152): peconv (512); [1152,5248): ln (4096, 2 rows each)
__global__ void __launch_bounds__(256) prep_kernel(
    const float* __restrict__ x, const float* __restrict__ lw, const float* __restrict__ lb,
    const float* __restrict__ w0, const float* __restrict__ w1, const float* __restrict__ w2,
    const float* __restrict__ w3, const float* __restrict__ w4, const float* __restrict__ pe,
    bf16* __restrict__ d0, bf16* __restrict__ d1, bf16* __restrict__ d2,
    bf16* __restrict__ d3, bf16* __restrict__ d4, bf16* __restrict__ dpe,
    bf16* __restrict__ hout)
{
    int bx = blockIdx.x;
    int tid = threadIdx.x;
    if (bx < 640) {
        int y = bx >> 7;
        const float* s = (y == 0) ? w0 : (y == 1) ? w1 : (y == 2) ? w2 : (y == 3) ? w3 : w4;
        bf16* d        = (y == 0) ? d0 : (y == 1) ? d1 : (y == 2) ? d2 : (y == 3) ? d3 : d4;
        int i = (bx & 127) * 256 + tid;
        float4 f0 = *((const float4*)s + i * 2);
        float4 f1 = *((const float4*)s + i * 2 + 1);
        *(uint4*)(d + i * 8) = make_uint4(pack_bf2(f0.x, f0.y), pack_bf2(f0.z, f0.w),
                                          pack_bf2(f1.x, f1.y), pack_bf2(f1.z, f1.w));
        return;
    }
    if (bx < 1152) {
        int i = (bx - 640) * 256 + tid;          // n8 = 131008 -> 512*256 = 131072, guard
        if (i >= CP * CD / 8) return;
        float4 f0 = *((const float4*)pe + i * 2);
        float4 f1 = *((const float4*)pe + i * 2 + 1);
        *(uint4*)(dpe + i * 8) = make_uint4(pack_bf2(f0.x, f0.y), pack_bf2(f0.z, f0.w),
                                            pack_bf2(f1.x, f1.y), pack_bf2(f1.z, f1.w));
        return;
    }
    // LayerNorm: 2 rows per block (threads 0-127 row A, 128-255 row B)
    int half = tid >> 7, t = tid & 127;
    int row = (bx - 1152) * 2 + half;
    const float* xr = x + (size_t)row * CD;
    float4 v = *(const float4*)(xr + t * 4);
    float s = v.x + v.y + v.z + v.w;
    #pragma unroll
    for (int o = 16; o; o >>= 1) s += __shfl_xor_sync(0xffffffffu, s, o);
    __shared__ float ws1[8], ws2[8];
    int w8 = tid >> 5;
    if ((t & 31) == 0) ws1[w8] = s;
    __syncthreads();
    int wb = half * 4;
    float mean = (ws1[wb] + ws1[wb+1] + ws1[wb+2] + ws1[wb+3]) * (1.0f / 512.0f);
    float dx = v.x - mean, dy = v.y - mean, dz = v.z - mean, dw = v.w - mean;
    float q = dx*dx + dy*dy + dz*dz + dw*dw;
    #pragma unroll
    for (int o = 16; o; o >>= 1) q += __shfl_xor_sync(0xffffffffu, q, o);
    if ((t & 31) == 0) ws2[w8] = q;
    __syncthreads();
    float var = (ws2[wb] + ws2[wb+1] + ws2[wb+2] + ws2[wb+3]) * (1.0f / 512.0f);
    float rstd = rsqrtf(var + 1e-5f);
    float4 wv = *(const float4*)(lw + t * 4);
    float4 bv = *(const float4*)(lb + t * 4);
    float ox = dx * rstd * wv.x + bv.x;
    float oy = dy * rstd * wv.y + bv.y;
    float oz = dz * rstd * wv.z + bv.z;
    float ow = dw * rstd * wv.w + bv.w;
    *(uint2*)(hout + (size_t)row * CD + t * 4) = make_uint2(pack_bf2(ox, oy), pack_bf2(oz, ow));
}

// ============================ GEMM core (bf16 mma, x4 B-frags, staged epilogue) ============================
constexpr int GKC  = 128 * 72;             // elems per stage buffer
constexpr int GSM_B = 4 * GKC * 2;         // 73,728 bytes dynamic

__device__ __forceinline__ void gemm_core(
    const bf16* __restrict__ A, int M,
    const bf16* __restrict__ W,
    const float* __restrict__ bias,
    const float* __restrict__ resid,
    void* __restrict__ outp, int mode,
    bf16* As, bf16* Ws)
{
    const int tid = threadIdx.x;
    const int l = tid & 31, wid = tid >> 5;
    const int wm = wid >> 1, wn = wid & 1;
    const int m0 = blockIdx.y * 128, n0 = blockIdx.x * 128;
    const int gid = l >> 2, tig = l & 3;
    const int lr = l & 7;
    const int g2 = l >> 3;
    const int a_row = ((l >> 3) & 1) * 8 + lr;
    const int a_col = (l >> 4) * 8;

    float4 cacc[2][8];
    #pragma unroll
    for (int mt = 0; mt < 2; mt++)
        #pragma unroll
        for (int nt = 0; nt < 8; nt++) cacc[mt][nt] = make_float4(0.f, 0.f, 0.f, 0.f);

    const unsigned aA = sptr(As) + ((wm * 32 + a_row) * 72 + a_col) * 2;
    const unsigned aB4 = sptr(Ws) + ((wn * 64 + (g2 >> 1) * 8 + lr) * 72 + (g2 & 1) * 8) * 2;

    uint4 ra[4], rw[4];
    auto ldg = [&](int k0) {
        #pragma unroll
        for (int it = 0; it < 4; it++) {
            int idx = tid + it * 256;
            int row = idx >> 3, seg = idx & 7;
            int kk = k0 + seg * 8;
            int am = m0 + row; if (am >= M) am = M - 1;
            ra[it] = *(const uint4*)(A + (size_t)am * 512 + kk);
            rw[it] = *(const uint4*)(W + (size_t)(n0 + row) * 512 + kk);
        }
    };
    auto sts = [&](int buf) {
        #pragma unroll
        for (int it = 0; it < 4; it++) {
            int idx = tid + it * 256;
            int row = idx >> 3, seg = idx & 7;
            *(uint4*)&As[buf * GKC + row * 72 + seg * 8] = ra[it];
            *(uint4*)&Ws[buf * GKC + row * 72 + seg * 8] = rw[it];
        }
    };

    ldg(0);
    sts(0);
    for (int c = 0; c < 8; c++) {
        if (c < 7) ldg((c + 1) * 64);
        __syncthreads();
        unsigned off = (unsigned)(c & 1) * (GKC * 2);
        #pragma unroll
        for (int ks = 0; ks < 4; ks++) {
            unsigned a0[4], a1[4];
            ldsm_x4(a0, aA + off + ks * 32);
            ldsm_x4(a1, aA + off + 16 * 144 + ks * 32);
            #pragma unroll
            for (int ntp = 0; ntp < 4; ntp++) {
                unsigned bb[4];
                ldsm_x4(bb, aB4 + off + ntp * (16 * 144) + ks * 32);
                mma16(cacc[0][2*ntp],   a0[0], a0[1], a0[2], a0[3], bb[0], bb[1]);
                mma16(cacc[1][2*ntp],   a1[0], a1[1], a1[2], a1[3], bb[0], bb[1]);
                mma16(cacc[0][2*ntp+1], a0[0], a0[1], a0[2], a0[3], bb[2], bb[3]);
                mma16(cacc[1][2*ntp+1], a1[0], a1[1], a1[2], a1[3], bb[2], bb[3]);
            }
        }
        if (c < 7) sts((c + 1) & 1);
    }

    if (mode == 4) {
        #pragma unroll
        for (int mt = 0; mt < 2; mt++) {
            #pragma unroll
            for (int nt = 0; nt < 8; nt++) {
                float4 c = cacc[mt][nt];
                int r0 = m0 + wm * 32 + mt * 16 + gid;
                int c0 = n0 + wn * 64 + nt * 8 + tig * 2;
                float vals[4] = {c.x, c.y, c.z, c.w};
                #pragma unroll
                for (int e = 0; e < 4; e++) {
                    int m = r0 + (e >= 2 ? 8 : 0);
                    int n = c0 + (e & 1);
                    size_t idx = (size_t)m * 512 + n;
                    ((float*)outp)[idx] = vals[e] + bias[n] + resid[idx];
                }
            }
        }
        return;
    }

    // staged coalesced epilogue for modes 0/3/5
    __syncthreads();
    bf16* Cst = As;                                  // [128][136]
    if (mode == 5) {
        #pragma unroll
        for (int mt = 0; mt < 2; mt++) {
            #pragma unroll
            for (int nt = 0; nt < 8; nt++) {
                float4 c = cacc[mt][nt];
                int r0 = wm * 32 + mt * 16 + gid;
                int c0 = wn * 64 + nt * 8 + tig * 2;
                float bx = bias[n0 + c0], by = bias[n0 + c0 + 1];
                Cst[c0 * 136 + r0]           = __float2bfloat16(c.x + bx);
                Cst[(c0 + 1) * 136 + r0]     = __float2bfloat16(c.y + by);
                Cst[c0 * 136 + r0 + 8]       = __float2bfloat16(c.z + bx);
                Cst[(c0 + 1) * 136 + r0 + 8] = __float2bfloat16(c.w + by);
            }
        }
    } else {
        #pragma unroll
        for (int mt = 0; mt < 2; mt++) {
            #pragma unroll
            for (int nt = 0; nt < 8; nt++) {
                float4 c = cacc[mt][nt];
                int r0 = wm * 32 + mt * 16 + gid;
                int c0 = wn * 64 + nt * 8 + tig * 2;
                float bx = (mode == 3) ? 0.f : bias[n0 + c0];
                float by = (mode == 3) ? 0.f : bias[n0 + c0 + 1];
                *(unsigned*)&Cst[r0 * 136 + c0]       = pack_bf2(c.x + bx, c.y + by);
                *(unsigned*)&Cst[(r0 + 8) * 136 + c0] = pack_bf2(c.z + bx, c.w + by);
            }
        }
    }
    __syncthreads();
    {
        int rl = tid & 127, hf = tid >> 7;
        const uint4* s4 = (const uint4*)(Cst + rl * 136 + hf * 64);
        if (mode == 5) {
            int n = n0 + rl, d = n & 63, hh = n >> 6;
            int mb = m0 + hf * 64;
            bf16* dst = (bf16*)outp + ((size_t)((mb >> 10) * CH + hh) << 16)
                        + (size_t)d * 1024 + (mb & 1023);
            #pragma unroll
            for (int i = 0; i < 8; i++) ((uint4*)dst)[i] = s4[i];
        } else if (mode == 0) {
            int m = m0 + rl;
            int hh = (n0 >> 6) + hf;
            bf16* dst = (bf16*)outp + ((size_t)((m >> 10) * CH + hh) << 16)
                        + (size_t)(m & 1023) * 64;
            #pragma unroll
            for (int i = 0; i < 8; i++) ((uint4*)dst)[i] = s4[i];
        } else {  // mode 3
            int m = m0 + rl;
            if (m < M) {
                int hh = (n0 >> 6) + hf;
                bf16* dst = (bf16*)outp + (size_t)hh * (CP * 64) + (size_t)m * 64;
                #pragma unroll
                for (int i = 0; i < 8; i++) ((uint4*)dst)[i] = s4[i];
            }
        }
    }
}

__global__ void __launch_bounds__(256, 2) gemm_kernel(
    const bf16* __restrict__ Ap, int M,
    const bf16* __restrict__ W, const float* __restrict__ bias,
    const float* __restrict__ resid, void* __restrict__ outp, int mode)
{
    extern __shared__ bf16 gsm[];
    gemm_core(Ap, M, W, bias, resid, outp, mode, gsm, gsm + 2 * GKC);
}

// fused QKV + pos projection: z in {0,1,2}: QKV; z==3: pos-gemm (y<16 only)
__global__ void __launch_bounds__(256, 2) qkv_kernel(
    const bf16* __restrict__ A,
    const bf16* __restrict__ Wq, const bf16* __restrict__ Wk, const bf16* __restrict__ Wv,
    const float* __restrict__ bq, const float* __restrict__ bk, const float* __restrict__ bv,
    bf16* __restrict__ q, bf16* __restrict__ k, bf16* __restrict__ v,
    const bf16* __restrict__ pe, const bf16* __restrict__ Wp, bf16* __restrict__ p)
{
    extern __shared__ bf16 gsm[];
    int z = blockIdx.z;
    if (z == 3) {
        if (blockIdx.y >= 16) return;
        gemm_core(pe, CP, Wp, nullptr, nullptr, p, 3, gsm, gsm + 2 * GKC);
        return;
    }
    const bf16* W     = (z == 0) ? Wq : (z == 1) ? Wk : Wv;
    const float* bias = (z == 0) ? bq : (z == 1) ? bk : bv;
    bf16* o           = (z == 0) ? q  : (z == 1) ? k  : v;
    gemm_core(A, MTOK, W, bias, nullptr, o, (z == 2) ? 5 : 0, gsm, gsm + 2 * GKC);
}

// ============================ Fused attention (bf16 scores, depth-2 pipelines) ============================
constexpr int SCH    = 1080;               // bf16 score stride (135*16B rows: ldsm conflict-free)
constexpr int SC_E   = 32 * SCH;           // 34560
constexpr int QT_E   = 32 * 72;            // 2304 each
constexpr int KB_E   = 128 * 72;           // 9216 per buffer (Vt 64*136=8704 fits)
constexpr int ASM_B  = (SC_E + 2 * QT_E + 2 * KB_E) * 2;   // 115,200 bytes -> 2 CTAs/SM

__global__ void __launch_bounds__(256, 2) attn_kernel(const float* __restrict__ bu,
    const float* __restrict__ bvp, bf16* __restrict__ ao)
{
    extern __shared__ bf16 smb[];
    bf16* sc   = smb;                  // [32][1080] bf16 scores/probs
    bf16* qut  = smb + SC_E;           // [32][72]
    bf16* qvt  = qut + QT_E;           // [32][72]
    bf16* kbuf = qvt + QT_E;           // 2 x [128][72] K/P chunks; Vt 2 x [64][136]

    const int tid = threadIdx.x;
    const int w = tid >> 5, l = tid & 31;
    const int gid = l >> 2, tig = l & 3;
    const int lr = l & 7;
    const int g2 = l >> 3;
    const int a_row = ((l >> 3) & 1) * 8 + lr;
    const int a_col = (l >> 4) * 8;
    const int qt = blockIdx.x & 31;
    const int bh = blockIdx.x >> 5;
    const int h  = bh & 7, b = bh >> 3;
    const int i0 = qt * 32;
    const bf16* qbase = g_q + (size_t)bh * (CS * CHD);
    const bf16* kbase = g_k + (size_t)bh * (CS * CHD);
    const bf16* vbase = g_v + (size_t)bh * (CS * CHD);   // [64][1024]
    const bf16* pbase = g_p + (size_t)h  * (CP * CHD);

    // ---- Phase A: q tile [32][72] bf16, both bias variants ----
    {
        int ii = tid >> 3, dq = (tid & 7) * 8;
        uint4 qw = *(const uint4*)(qbase + (size_t)(i0 + ii) * 64 + dq);
        unsigned wsv[4] = {qw.x, qw.y, qw.z, qw.w};
        unsigned uo[4], vo[4];
        #pragma unroll
        for (int j = 0; j < 4; j++) {
            float fx = bf_lo(wsv[j]), fy = bf_hi(wsv[j]);
            int d = dq + 2 * j;
            uo[j] = pack_bf2(fx + bu [h*64+d], fy + bu [h*64+d+1]);
            vo[j] = pack_bf2(fx + bvp[h*64+d], fy + bvp[h*64+d+1]);
        }
        *(uint4*)&qut[ii * 72 + dq] = make_uint4(uo[0], uo[1], uo[2], uo[3]);
        *(uint4*)&qvt[ii * 72 + dq] = make_uint4(vo[0], vo[1], vo[2], vo[3]);
    }

    const unsigned aQU = sptr(qut) + (a_row * 72 + a_col) * 2;
    const unsigned aQV = sptr(qvt) + (a_row * 72 + a_col) * 2;
    const unsigned aKB4 = sptr(kbuf) + ((w * 16 + (g2 >> 1) * 8 + lr) * 72 + (g2 & 1) * 8) * 2;
    constexpr unsigned KBB = KB_E * 2;
    const int rlo = 992 - i0;
    const int srow = tid >> 1;                 // K/P staging: 128 rows, 2 thr/row
    const int sseg = (tid & 1) * 4;

    auto ldgP = [&](int ch, uint4* r) {
        int rr = rlo + ch * 128 + srow; if (rr > 2046) rr = 2046; if (rr < 0) rr = 0;
        const bf16* src = pbase + (size_t)rr * 64;
        #pragma unroll
        for (int it = 0; it < 4; it++) r[it] = *(const uint4*)(src + (sseg + it) * 8);
    };
    auto ldgK = [&](int ch, uint4* r) {
        const bf16* src = kbase + (size_t)(ch * 128 + srow) * 64;
        #pragma unroll
        for (int it = 0; it < 4; it++) r[it] = *(const uint4*)(src + (sseg + it) * 8);
    };
    auto stsK = [&](int buf, const uint4* r) {
        #pragma unroll
        for (int it = 0; it < 4; it++)
            *(uint4*)&kbuf[buf * KB_E + srow * 72 + (sseg + it) * 8] = r[it];
    };

    // ======== Phase B1: pos scores (9 chunks of 128), depth-2 pipeline ========
    {
        uint4 rA[4], rB[4];
        ldgP(0, rA); ldgP(1, rB);
        __syncthreads();                       // publish qut/qvt; kbuf free
        stsK(0, rA);
        unsigned af[2][4][4];
        #pragma unroll
        for (int ks = 0; ks < 4; ks++) {
            ldsm_x4(af[0][ks], aQV + ks * 32);
            ldsm_x4(af[1][ks], aQV + 16 * 144 + ks * 32);
        }
        auto comp = [&](int ch, unsigned off) {
            float4 cacc[2][2];
            #pragma unroll
            for (int mt = 0; mt < 2; mt++)
                #pragma unroll
                for (int nt = 0; nt < 2; nt++) cacc[mt][nt] = make_float4(0.f,0.f,0.f,0.f);
            #pragma unroll
            for (int ks = 0; ks < 4; ks++) {
                unsigned bb[4];
                ldsm_x4(bb, aKB4 + off + ks * 32);
                mma16(cacc[0][0], af[0][ks][0], af[0][ks][1], af[0][ks][2], af[0][ks][3], bb[0], bb[1]);
                mma16(cacc[1][0], af[1][ks][0], af[1][ks][1], af[1][ks][2], af[1][ks][3], bb[0], bb[1]);
                mma16(cacc[0][1], af[0][ks][0], af[0][ks][1], af[0][ks][2], af[0][ks][3], bb[2], bb[3]);
                mma16(cacc[1][1], af[1][ks][0], af[1][ks][1], af[1][ks][2], af[1][ks][3], bb[2], bb[3]);
            }
            if (ch == 0 || ch == 8) {
                #pragma unroll
                for (int mt = 0; mt < 2; mt++) {
                    #pragma unroll
                    for (int nt = 0; nt < 2; nt++) {
                        float4 c = cacc[mt][nt];
                        int ii = mt * 16 + gid;
                        int rr = ch * 128 + w * 16 + nt * 8 + tig * 2;
                        int jx = rr + ii - 31;
                        if (jx >= 0 && jx < 1024)         sc[ii * SCH + jx]     = __float2bfloat16(c.x);
                        if (jx + 1 >= 0 && jx + 1 < 1024) sc[ii * SCH + jx + 1] = __float2bfloat16(c.y);
                        int jz = jx + 8, i2 = ii + 8;
                        if (jz >= 0 && jz < 1024)         sc[i2 * SCH + jz]     = __float2bfloat16(c.z);
                        if (jz + 1 >= 0 && jz + 1 < 1024) sc[i2 * SCH + jz + 1] = __float2bfloat16(c.w);
                    }
                }
            } else {
                #pragma unroll
                for (int mt = 0; mt < 2; mt++) {
                    #pragma unroll
                    for (int nt = 0; nt < 2; nt++) {
                        float4 c = cacc[mt][nt];
                        int ii = mt * 16 + gid;
                        int jx = ch * 128 + w * 16 + nt * 8 + tig * 2 + ii - 31;
                        sc[ii * SCH + jx]           = __float2bfloat16(c.x);
                        sc[ii * SCH + jx + 1]       = __float2bfloat16(c.y);
                        sc[(ii + 8) * SCH + jx + 8] = __float2bfloat16(c.z);
                        sc[(ii + 8) * SCH + jx + 9] = __float2bfloat16(c.w);
                    }
                }
            }
        };
        #pragma unroll 1
        for (int c = 0; c < 8; c += 2) {
            ldgP(c + 2, rA);
            __syncthreads();
            stsK(1, rB);
            comp(c, 0u);
            if (c < 6) ldgP(c + 3, rB);
            __syncthreads();
            stsK(0, rA);
            comp(c + 1, KBB);
        }
        __syncthreads();
        comp(8, 0u);
    }

    // ======== Phase B2: content scores (8 chunks of 128), depth-2, bf16 RMW ========
    {
        uint4 rA[4], rB[4];
        ldgK(0, rA); ldgK(1, rB);
        __syncthreads();
        stsK(0, rA);
        unsigned af[2][4][4];
        #pragma unroll
        for (int ks = 0; ks < 4; ks++) {
            ldsm_x4(af[0][ks], aQU + ks * 32);
            ldsm_x4(af[1][ks], aQU + 16 * 144 + ks * 32);
        }
        auto comp = [&](int ch, unsigned off) {
            float4 cacc[2][2];
            #pragma unroll
            for (int mt = 0; mt < 2; mt++)
                #pragma unroll
                for (int nt = 0; nt < 2; nt++) cacc[mt][nt] = make_float4(0.f,0.f,0.f,0.f);
            #pragma unroll
            for (int ks = 0; ks < 4; ks++) {
                unsigned bb[4];
                ldsm_x4(bb, aKB4 + off + ks * 32);
                mma16(cacc[0][0], af[0][ks][0], af[0][ks][1], af[0][ks][2], af[0][ks][3], bb[0], bb[1]);
                mma16(cacc[1][0], af[1][ks][0], af[1][ks][1], af[1][ks][2], af[1][ks][3], bb[0], bb[1]);
                mma16(cacc[0][1], af[0][ks][0], af[0][ks][1], af[0][ks][2], af[0][ks][3], bb[2], bb[3]);
                mma16(cacc[1][1], af[1][ks][0], af[1][ks][1], af[1][ks][2], af[1][ks][3], bb[2], bb[3]);
            }
            #pragma unroll
            for (int mt = 0; mt < 2; mt++) {
                #pragma unroll
                for (int nt = 0; nt < 2; nt++) {
                    float4 c = cacc[mt][nt];
                    int ii = mt * 16 + gid;
                    int col = ch * 128 + w * 16 + nt * 8 + tig * 2;
                    unsigned* p0 = (unsigned*)&sc[ii * SCH + col];
                    unsigned u0 = *p0;
                    *p0 = pack_bf2(bf_lo(u0) + c.x, bf_hi(u0) + c.y);
                    unsigned* p1 = (unsigned*)&sc[(ii + 8) * SCH + col];
                    unsigned u1 = *p1;
                    *p1 = pack_bf2(bf_lo(u1) + c.z, bf_hi(u1) + c.w);
                }
            }
        };
        #pragma unroll 1
        for (int c = 0; c < 8; c += 2) {
            if (c < 6) ldgK(c + 2, rA);
            __syncthreads();
            stsK(1, rB);
            comp(c, 0u);
            if (c < 5) ldgK(c + 3, rB);
            __syncthreads();
            if (c < 6) stsK(0, rA);
            comp(c + 1, KBB);
        }
    }
    __syncthreads();

    // ======== Phase C: softmax (scale 1/8 inside exp), 4 rows per warp ========
    #pragma unroll
    for (int rr = 0; rr < 4; rr++) {
        int row = w * 4 + rr;
        bf16* rp = sc + row * SCH;
        unsigned u[16];
        float f[32];
        #pragma unroll
        for (int g = 0; g < 4; g++) {
            uint4 q4 = *(const uint4*)(rp + g * 256 + l * 8);
            u[g*4+0] = q4.x; u[g*4+1] = q4.y; u[g*4+2] = q4.z; u[g*4+3] = q4.w;
        }
        float mx = -1e30f;
        #pragma unroll
        for (int e = 0; e < 16; e++) {
            f[2*e]   = bf_lo(u[e]);
            f[2*e+1] = bf_hi(u[e]);
            mx = fmaxf(mx, fmaxf(f[2*e], f[2*e+1]));
        }
        #pragma unroll
        for (int o = 16; o; o >>= 1) mx = fmaxf(mx, __shfl_xor_sync(0xffffffffu, mx, o));
        float sum = 0.f;
        #pragma unroll
        for (int e = 0; e < 32; e++) {
            f[e] = __expf((f[e] - mx) * 0.125f);
            sum += f[e];
        }
        #pragma unroll
        for (int o = 16; o; o >>= 1) sum += __shfl_xor_sync(0xffffffffu, sum, o);
        float inv = 1.0f / sum;
        #pragma unroll
        for (int g = 0; g < 4; g++) {
            uint4 q4;
            q4.x = pack_bf2(f[g*8+0] * inv, f[g*8+1] * inv);
            q4.y = pack_bf2(f[g*8+2] * inv, f[g*8+3] * inv);
            q4.z = pack_bf2(f[g*8+4] * inv, f[g*8+5] * inv);
            q4.w = pack_bf2(f[g*8+6] * inv, f[g*8+7] * inv);
            *(uint4*)(rp + g * 256 + l * 8) = q4;
        }
    }

    // ======== Phase D: O = attn @ V (8 chunks of 128 keys), depth-2, 8-way k-split ========
    const int vrow = tid >> 2;                 // V staging: 64 rows, 4 thr/row
    const int vseg = (tid & 3) * 4;
    const unsigned aVT4 = sptr(kbuf) + (((g2 >> 1) * 8 + lr) * 136 + w * 16 + (g2 & 1) * 8) * 2;
    auto ldgV = [&](int ch, uint4* r) {
        const bf16* src = vbase + (size_t)vrow * 1024 + ch * 128;
        #pragma unroll
        for (int it = 0; it < 4; it++) r[it] = *(const uint4*)(src + (vseg + it) * 8);
    };
    auto stsV = [&](int buf, const uint4* r) {
        #pragma unroll
        for (int it = 0; it < 4; it++)
            *(uint4*)&kbuf[buf * KB_E + vrow * 136 + (vseg + it) * 8] = r[it];
    };

    float4 oacc[2][8];
    #pragma unroll
    for (int mt = 0; mt < 2; mt++)
        #pragma unroll
        for (int nt = 0; nt < 8; nt++) oacc[mt][nt] = make_float4(0.f,0.f,0.f,0.f);

    auto compD = [&](int ch, unsigned off) {
        unsigned a0[4], a1[4];
        ldsm_x4(a0, sptr(sc) + (a_row * SCH + ch * 128 + w * 16 + a_col) * 2);
        ldsm_x4(a1, sptr(sc) + ((16 + a_row) * SCH + ch * 128 + w * 16 + a_col) * 2);
        #pragma unroll
        for (int ntp = 0; ntp < 4; ntp++) {
            unsigned bb[4];
            ldsm_x4(bb, aVT4 + off + ntp * (16 * 272));
            mma16(oacc[0][2*ntp],   a0[0], a0[1], a0[2], a0[3], bb[0], bb[1]);
            mma16(oacc[1][2*ntp],   a1[0], a1[1], a1[2], a1[3], bb[0], bb[1]);
            mma16(oacc[0][2*ntp+1], a0[0], a0[1], a0[2], a0[3], bb[2], bb[3]);
            mma16(oacc[1][2*ntp+1], a1[0], a1[1], a1[2], a1[3], bb[2], bb[3]);
        }
    };
    {
        uint4 rA[4], rB[4];
        ldgV(0, rA); ldgV(1, rB);
        __syncthreads();                       // publish softmax sc; kbuf free
        stsV(0, rA);
        #pragma unroll 1
        for (int c = 0; c < 8; c += 2) {
            if (c < 6) ldgV(c + 2, rA);
            __syncthreads();
            stsV(1, rB);
            compD(c, 0u);
            if (c < 5) ldgV(c + 3, rB);
            __syncthreads();
            if (c < 6) stsV(0, rA);
            compD(c + 1, KBB);
        }
    }

    // per-warp partials -> fp32 overlay over sc (probs dead), then cross-warp reduce
    __syncthreads();
    float* ovl = (float*)sc;
    {
        float* pb = ovl + w * 2176;
        #pragma unroll
        for (int mt = 0; mt < 2; mt++) {
            #pragma unroll
            for (int nt = 0; nt < 8; nt++) {
                float4 c = oacc[mt][nt];
                int r = mt * 16 + gid;
                int cc = nt * 8 + tig * 2;
                pb[r * 68 + cc]           = c.x;
                pb[r * 68 + cc + 1]       = c.y;
                pb[(r + 8) * 68 + cc]     = c.z;
                pb[(r + 8) * 68 + cc + 1] = c.w;
            }
        }
    }
    __syncthreads();
    #pragma unroll
    for (int rep = 0; rep < 2; rep++) {
        int e = tid + rep * 256;
        int row = e >> 4, d4 = (e & 15) * 4;
        float4 s = make_float4(0.f, 0.f, 0.f, 0.f);
        #pragma unroll
        for (int ww = 0; ww < 8; ww++) {
            float4 p4 = *(const float4*)&ovl[ww * 2176 + row * 68 + d4];
            s.x += p4.x; s.y += p4.y; s.z += p4.z; s.w += p4.w;
        }
        *(uint2*)(ao + (size_t)(b * 1024 + i0 + row) * 512 + h * 64 + d4)
            = make_uint2(pack_bf2(s.x, s.y), pack_bf2(s.z, s.w));
    }
}

// ============================ launch ============================
extern "C" void kernel_launch(void* const* d_in, const int* in_sizes, int n_in,
                              void* d_out, int out_size)
{
    const float* x       = (const float*)d_in[0];
    const float* pos_emb = (const float*)d_in[1];
    const float* ln_w    = (const float*)d_in[2];
    const float* ln_b    = (const float*)d_in[3];
    const float* Wq      = (const float*)d_in[4];
    const float* bq      = (const float*)d_in[5];
    const float* Wk      = (const float*)d_in[6];
    const float* bk      = (const float*)d_in[7];
    const float* Wv      = (const float*)d_in[8];
    const float* bv      = (const float*)d_in[9];
    const float* Wo      = (const float*)d_in[10];
    const float* bo      = (const float*)d_in[11];
    const float* Wp      = (const float*)d_in[12];
    const float* pbu     = (const float*)d_in[13];
    const float* pbv     = (const float*)d_in[14];
    float* out = (float*)d_out;

    bf16 *hp, *qp, *kp, *vp, *pp, *aop;
    bf16 *wqp, *wkp, *wvp, *wop, *wpp, *pep;
    cudaGetSymbolAddress((void**)&hp,  g_h);
    cudaGetSymbolAddress((void**)&qp,  g_q);
    cudaGetSymbolAddress((void**)&kp,  g_k);
    cudaGetSymbolAddress((void**)&vp,  g_v);
    cudaGetSymbolAddress((void**)&pp,  g_p);
    cudaGetSymbolAddress((void**)&aop, g_ao);
    cudaGetSymbolAddress((void**)&wqp, g_wq);
    cudaGetSymbolAddress((void**)&wkp, g_wk);
    cudaGetSymbolAddress((void**)&wvp, g_wv);
    cudaGetSymbolAddress((void**)&wop, g_wo);
    cudaGetSymbolAddress((void**)&wpp, g_wp);
    cudaGetSymbolAddress((void**)&pep, g_pe);

    cudaFuncSetAttribute(attn_kernel, cudaFuncAttributeMaxDynamicSharedMemorySize, ASM_B);
    cudaFuncSetAttribute(gemm_kernel, cudaFuncAttributeMaxDynamicSharedMemorySize, GSM_B);
    cudaFuncSetAttribute(qkv_kernel,  cudaFuncAttributeMaxDynamicSharedMemorySize, GSM_B);

    prep_kernel<<<5248, 256>>>(x, ln_w, ln_b, Wq, Wk, Wv, Wo, Wp, pos_emb,
                               wqp, wkp, wvp, wop, wpp, pep, hp);

    qkv_kernel<<<dim3(4, 64, 4), 256, GSM_B>>>(hp, wqp, wkp, wvp, bq, bk, bv,
                                               qp, kp, vp, pep, wpp, pp);

    attn_kernel<<<CB * CH * (CS / 32), 256, ASM_B>>>(pbu, pbv, aop);

    gemm_kernel<<<dim3(4, 64), 256, GSM_B>>>(aop, MTOK, wop, bo, x, out, 4);
}

// round 15
// speedup vs baseline: 1.4688x; 1.4688x over previous
#include <cuda_runtime.h>
#include <cuda_bf16.h>

// ConformerAttention: B=8, S=1024, D=512, H=8, hd=64, P=2047
// rel_shift identity: shifted[i,j] = raw[i, j + (S-1) - i] -> p row r = 1023 + j - i.
// 32-row q tiles: rlo = 992 - i0, j = rr + ii - 31.

#define CB 8
#define CS 1024
#define CD 512
#define CH 8
#define CHD 64
#define CP 2047
#define MTOK (CB*CS)   // 8192

typedef __nv_bfloat16 bf16;

__device__ __forceinline__ unsigned pack_bf2(float lo, float hi) {
    unsigned r; asm("cvt.rn.bf16x2.f32 %0, %1, %2;" : "=r"(r) : "f"(hi), "f"(lo)); return r;
}
__device__ __forceinline__ float bf_lo(unsigned u) { return __uint_as_float(u << 16); }
__device__ __forceinline__ float bf_hi(unsigned u) { return __uint_as_float(u & 0xFFFF0000u); }

__device__ __forceinline__ void mma16(float4& c, unsigned a0, unsigned a1, unsigned a2, unsigned a3,
                                      unsigned b0, unsigned b1) {
    asm volatile(
        "mma.sync.aligned.m16n8k16.row.col.f32.bf16.bf16.f32 "
        "{%0,%1,%2,%3}, {%4,%5,%6,%7}, {%8,%9}, {%0,%1,%2,%3};"
        : "+f"(c.x), "+f"(c.y), "+f"(c.z), "+f"(c.w)
        : "r"(a0), "r"(a1), "r"(a2), "r"(a3), "r"(b0), "r"(b1));
}
__device__ __forceinline__ unsigned sptr(const void* p) {
    return (unsigned)__cvta_generic_to_shared(p);
}
__device__ __forceinline__ void ldsm_x4(unsigned* r, unsigned addr) {
    asm volatile("ldmatrix.sync.aligned.m8n8.x4.shared.b16 {%0,%1,%2,%3}, [%4];"
        : "=r"(r[0]), "=r"(r[1]), "=r"(r[2]), "=r"(r[3]) : "r"(addr));
}

// -------- scratch (allocation-free: device globals) --------
__device__ bf16 g_h [MTOK*CD];
__device__ bf16 g_q [CB*CH*CS*CHD];      // [bh][S][hd]
__device__ bf16 g_k [CB*CH*CS*CHD];      // [bh][S][hd]
__device__ bf16 g_v [CB*CH*CS*CHD];      // [bh][hd][S]  (pre-transposed, mode 5)
__device__ bf16 g_p [CH*CP*CHD];         // [H][P][hd]
__device__ bf16 g_ao[MTOK*CD];           // [B,S,D]
__device__ bf16 g_wq[CD*CD], g_wk[CD*CD], g_wv[CD*CD], g_wo[CD*CD], g_wp[CD*CD];
__device__ bf16 g_pe[CP*CD];             // pos_emb bf16

// ============================ fp32 -> bf16 conversions ============================
__global__ void __launch_bounds__(256) wconv_kernel(
    const float* __restrict__ w0, const float* __restrict__ w1, const float* __restrict__ w2,
    const float* __restrict__ w3, const float* __restrict__ w4,
    bf16* __restrict__ d0, bf16* __restrict__ d1, bf16* __restrict__ d2,
    bf16* __restrict__ d3, bf16* __restrict__ d4)
{
    int y = blockIdx.y;
    const float* s = (y == 0) ? w0 : (y == 1) ? w1 : (y == 2) ? w2 : (y == 3) ? w3 : w4;
    bf16* d        = (y == 0) ? d0 : (y == 1) ? d1 : (y == 2) ? d2 : (y == 3) ? d3 : d4;
    int i = blockIdx.x * 256 + threadIdx.x;
    float4 f0 = *((const float4*)s + i * 2);
    float4 f1 = *((const float4*)s + i * 2 + 1);
    *(uint4*)(d + i * 8) = make_uint4(pack_bf2(f0.x, f0.y), pack_bf2(f0.z, f0.w),
                                      pack_bf2(f1.x, f1.y), pack_bf2(f1.z, f1.w));
}
__global__ void __launch_bounds__(256) peconv_kernel(const float* __restrict__ s, bf16* __restrict__ d, int n8)
{
    int i = blockIdx.x * 256 + threadIdx.x;
    if (i >= n8) return;
    float4 f0 = *((const float4*)s + i * 2);
    float4 f1 = *((const float4*)s + i * 2 + 1);
    *(uint4*)(d + i * 8) = make_uint4(pack_bf2(f0.x, f0.y), pack_bf2(f0.z, f0.w),
                                      pack_bf2(f1.x, f1.y), pack_bf2(f1.z, f1.w));
}

// ============================ LayerNorm (fp32 in -> bf16 out) ============================
__global__ void __launch_bounds__(128) ln_kernel(const float* __restrict__ x,
    const float* __restrict__ w, const float* __restrict__ b, bf16* __restrict__ out)
{
    int row = blockIdx.x;
    int t = threadIdx.x;
    const float* xr = x + (size_t)row * CD;
    float4 v = *(const float4*)(xr + t * 4);
    float s = v.x + v.y + v.z + v.w;
    #pragma unroll
    for (int o = 16; o; o >>= 1) s += __shfl_xor_sync(0xffffffffu, s, o);
    __shared__ float ws1[4], ws2[4];
    if ((t & 31) == 0) ws1[t >> 5] = s;
    __syncthreads();
    float mean = (ws1[0] + ws1[1] + ws1[2] + ws1[3]) * (1.0f / 512.0f);
    float dx = v.x - mean, dy = v.y - mean, dz = v.z - mean, dw = v.w - mean;
    float q = dx*dx + dy*dy + dz*dz + dw*dw;
    #pragma unroll
    for (int o = 16; o; o >>= 1) q += __shfl_xor_sync(0xffffffffu, q, o);
    if ((t & 31) == 0) ws2[t >> 5] = q;
    __syncthreads();
    float var = (ws2[0] + ws2[1] + ws2[2] + ws2[3]) * (1.0f / 512.0f);
    float rstd = rsqrtf(var + 1e-5f);
    float4 wv = *(const float4*)(w + t * 4);
    float4 bv = *(const float4*)(b + t * 4);
    float ox = dx * rstd * wv.x + bv.x;
    float oy = dy * rstd * wv.y + bv.y;
    float oz = dz * rstd * wv.z + bv.z;
    float ow = dw * rstd * wv.w + bv.w;
    *(uint2*)(out + (size_t)row * CD + t * 4) = make_uint2(pack_bf2(ox, oy), pack_bf2(oz, ow));
}

// ============================ GEMM core (bf16 mma, x4 B-frags, staged epilogue) ============================
constexpr int GKC  = 128 * 72;             // elems per stage buffer
constexpr int GSM_B = 4 * GKC * 2;         // 73,728 bytes dynamic

__device__ __forceinline__ void gemm_core(
    const bf16* __restrict__ A, int M,
    const bf16* __restrict__ W,
    const float* __restrict__ bias,
    const float* __restrict__ resid,
    void* __restrict__ outp, int mode,
    bf16* As, bf16* Ws)
{
    const int tid = threadIdx.x;
    const int l = tid & 31, wid = tid >> 5;
    const int wm = wid >> 1, wn = wid & 1;
    const int m0 = blockIdx.y * 128, n0 = blockIdx.x * 128;
    const int gid = l >> 2, tig = l & 3;
    const int lr = l & 7;
    const int g2 = l >> 3;
    const int a_row = ((l >> 3) & 1) * 8 + lr;
    const int a_col = (l >> 4) * 8;

    float4 cacc[2][8];
    #pragma unroll
    for (int mt = 0; mt < 2; mt++)
        #pragma unroll
        for (int nt = 0; nt < 8; nt++) cacc[mt][nt] = make_float4(0.f, 0.f, 0.f, 0.f);

    const unsigned aA = sptr(As) + ((wm * 32 + a_row) * 72 + a_col) * 2;
    const unsigned aB4 = sptr(Ws) + ((wn * 64 + (g2 >> 1) * 8 + lr) * 72 + (g2 & 1) * 8) * 2;

    uint4 ra[4], rw[4];
    auto ldg = [&](int k0) {
        #pragma unroll
        for (int it = 0; it < 4; it++) {
            int idx = tid + it * 256;
            int row = idx >> 3, seg = idx & 7;
            int kk = k0 + seg * 8;
            int am = m0 + row; if (am >= M) am = M - 1;
            ra[it] = *(const uint4*)(A + (size_t)am * 512 + kk);
            rw[it] = *(const uint4*)(W + (size_t)(n0 + row) * 512 + kk);
        }
    };
    auto sts = [&](int buf) {
        #pragma unroll
        for (int it = 0; it < 4; it++) {
            int idx = tid + it * 256;
            int row = idx >> 3, seg = idx & 7;
            *(uint4*)&As[buf * GKC + row * 72 + seg * 8] = ra[it];
            *(uint4*)&Ws[buf * GKC + row * 72 + seg * 8] = rw[it];
        }
    };

    ldg(0);
    sts(0);
    for (int c = 0; c < 8; c++) {
        if (c < 7) ldg((c + 1) * 64);
        __syncthreads();
        unsigned off = (unsigned)(c & 1) * (GKC * 2);
        #pragma unroll
        for (int ks = 0; ks < 4; ks++) {
            unsigned a0[4], a1[4];
            ldsm_x4(a0, aA + off + ks * 32);
            ldsm_x4(a1, aA + off + 16 * 144 + ks * 32);
            #pragma unroll
            for (int ntp = 0; ntp < 4; ntp++) {
                unsigned bb[4];
                ldsm_x4(bb, aB4 + off + ntp * (16 * 144) + ks * 32);
                mma16(cacc[0][2*ntp],   a0[0], a0[1], a0[2], a0[3], bb[0], bb[1]);
                mma16(cacc[1][2*ntp],   a1[0], a1[1], a1[2], a1[3], bb[0], bb[1]);
                mma16(cacc[0][2*ntp+1], a0[0], a0[1], a0[2], a0[3], bb[2], bb[3]);
                mma16(cacc[1][2*ntp+1], a1[0], a1[1], a1[2], a1[3], bb[2], bb[3]);
            }
        }
        if (c < 7) sts((c + 1) & 1);
    }

    if (mode == 4) {
        #pragma unroll
        for (int mt = 0; mt < 2; mt++) {
            #pragma unroll
            for (int nt = 0; nt < 8; nt++) {
                float4 c = cacc[mt][nt];
                int r0 = m0 + wm * 32 + mt * 16 + gid;
                int c0 = n0 + wn * 64 + nt * 8 + tig * 2;
                float vals[4] = {c.x, c.y, c.z, c.w};
                #pragma unroll
                for (int e = 0; e < 4; e++) {
                    int m = r0 + (e >= 2 ? 8 : 0);
                    int n = c0 + (e & 1);
                    size_t idx = (size_t)m * 512 + n;
                    ((float*)outp)[idx] = vals[e] + bias[n] + resid[idx];
                }
            }
        }
        return;
    }

    // staged coalesced epilogue for modes 0/3/5
    __syncthreads();
    bf16* Cst = As;                                  // [128][136]
    if (mode == 5) {
        #pragma unroll
        for (int mt = 0; mt < 2; mt++) {
            #pragma unroll
            for (int nt = 0; nt < 8; nt++) {
                float4 c = cacc[mt][nt];
                int r0 = wm * 32 + mt * 16 + gid;
                int c0 = wn * 64 + nt * 8 + tig * 2;
                float bx = bias[n0 + c0], by = bias[n0 + c0 + 1];
                Cst[c0 * 136 + r0]           = __float2bfloat16(c.x + bx);
                Cst[(c0 + 1) * 136 + r0]     = __float2bfloat16(c.y + by);
                Cst[c0 * 136 + r0 + 8]       = __float2bfloat16(c.z + bx);
                Cst[(c0 + 1) * 136 + r0 + 8] = __float2bfloat16(c.w + by);
            }
        }
    } else {
        #pragma unroll
        for (int mt = 0; mt < 2; mt++) {
            #pragma unroll
            for (int nt = 0; nt < 8; nt++) {
                float4 c = cacc[mt][nt];
                int r0 = wm * 32 + mt * 16 + gid;
                int c0 = wn * 64 + nt * 8 + tig * 2;
                float bx = (mode == 3) ? 0.f : bias[n0 + c0];
                float by = (mode == 3) ? 0.f : bias[n0 + c0 + 1];
                *(unsigned*)&Cst[r0 * 136 + c0]       = pack_bf2(c.x + bx, c.y + by);
                *(unsigned*)&Cst[(r0 + 8) * 136 + c0] = pack_bf2(c.z + bx, c.w + by);
            }
        }
    }
    __syncthreads();
    {
        int rl = tid & 127, hf = tid >> 7;
        const uint4* s4 = (const uint4*)(Cst + rl * 136 + hf * 64);
        if (mode == 5) {
            int n = n0 + rl, d = n & 63, hh = n >> 6;
            int mb = m0 + hf * 64;
            bf16* dst = (bf16*)outp + ((size_t)((mb >> 10) * CH + hh) << 16)
                        + (size_t)d * 1024 + (mb & 1023);
            #pragma unroll
            for (int i = 0; i < 8; i++) ((uint4*)dst)[i] = s4[i];
        } else if (mode == 0) {
            int m = m0 + rl;
            int hh = (n0 >> 6) + hf;
            bf16* dst = (bf16*)outp + ((size_t)((m >> 10) * CH + hh) << 16)
                        + (size_t)(m & 1023) * 64;
            #pragma unroll
            for (int i = 0; i < 8; i++) ((uint4*)dst)[i] = s4[i];
        } else {  // mode 3
            int m = m0 + rl;
            if (m < M) {
                int hh = (n0 >> 6) + hf;
                bf16* dst = (bf16*)outp + (size_t)hh * (CP * 64) + (size_t)m * 64;
                #pragma unroll
                for (int i = 0; i < 8; i++) ((uint4*)dst)[i] = s4[i];
            }
        }
    }
}

__global__ void __launch_bounds__(256, 2) gemm_kernel(
    const bf16* __restrict__ Ap, int M,
    const bf16* __restrict__ W, const float* __restrict__ bias,
    const float* __restrict__ resid, void* __restrict__ outp, int mode)
{
    extern __shared__ bf16 gsm[];
    gemm_core(Ap, M, W, bias, resid, outp, mode, gsm, gsm + 2 * GKC);
}

__global__ void __launch_bounds__(256, 2) qkv_kernel(
    const bf16* __restrict__ A,
    const bf16* __restrict__ Wq, const bf16* __restrict__ Wk, const bf16* __restrict__ Wv,
    const float* __restrict__ bq, const float* __restrict__ bk, const float* __restrict__ bv,
    bf16* __restrict__ q, bf16* __restrict__ k, bf16* __restrict__ v)
{
    extern __shared__ bf16 gsm[];
    int z = blockIdx.z;
    const bf16* W     = (z == 0) ? Wq : (z == 1) ? Wk : Wv;
    const float* bias = (z == 0) ? bq : (z == 1) ? bk : bv;
    bf16* o           = (z == 0) ? q  : (z == 1) ? k  : v;
    gemm_core(A, MTOK, W, bias, nullptr, o, (z == 2) ? 5 : 0, gsm, gsm + 2 * GKC);
}

// ============================ Fused attention (bf16 scores, depth-2 pipelines) ============================
constexpr int SCH    = 1080;               // bf16 score stride (135*16B rows: ldsm conflict-free)
constexpr int SC_E   = 32 * SCH;           // 34560
constexpr int QT_E   = 32 * 72;            // 2304 each
constexpr int KB_E   = 128 * 72;           // 9216 per buffer (Vt 64*136=8704 fits)
constexpr int ASM_B  = (SC_E + 2 * QT_E + 2 * KB_E) * 2;   // 115,200 bytes -> 2 CTAs/SM

__global__ void __launch_bounds__(256, 2) attn_kernel(const float* __restrict__ bu,
    const float* __restrict__ bvp, bf16* __restrict__ ao)
{
    extern __shared__ bf16 smb[];
    bf16* sc   = smb;                  // [32][1080] bf16 scores/probs
    bf16* qut  = smb + SC_E;           // [32][72]
    bf16* qvt  = qut + QT_E;           // [32][72]
    bf16* kbuf = qvt + QT_E;           // 2 x [128][72] K/P chunks; Vt 2 x [64][136]

    const int tid = threadIdx.x;
    const int w = tid >> 5, l = tid & 31;
    const int gid = l >> 2, tig = l & 3;
    const int lr = l & 7;
    const int g2 = l >> 3;
    const int a_row = ((l >> 3) & 1) * 8 + lr;
    const int a_col = (l >> 4) * 8;
    const int qt = blockIdx.x & 31;
    const int bh = blockIdx.x >> 5;
    const int h  = bh & 7, b = bh >> 3;
    const int i0 = qt * 32;
    const bf16* qbase = g_q + (size_t)bh * (CS * CHD);
    const bf16* kbase = g_k + (size_t)bh * (CS * CHD);
    const bf16* vbase = g_v + (size_t)bh * (CS * CHD);   // [64][1024]
    const bf16* pbase = g_p + (size_t)h  * (CP * CHD);

    // ---- Phase A: q tile [32][72] bf16, both bias variants ----
    {
        int ii = tid >> 3, dq = (tid & 7) * 8;
        uint4 qw = *(const uint4*)(qbase + (size_t)(i0 + ii) * 64 + dq);
        unsigned wsv[4] = {qw.x, qw.y, qw.z, qw.w};
        unsigned uo[4], vo[4];
        #pragma unroll
        for (int j = 0; j < 4; j++) {
            float fx = bf_lo(wsv[j]), fy = bf_hi(wsv[j]);
            int d = dq + 2 * j;
            uo[j] = pack_bf2(fx + bu [h*64+d], fy + bu [h*64+d+1]);
            vo[j] = pack_bf2(fx + bvp[h*64+d], fy + bvp[h*64+d+1]);
        }
        *(uint4*)&qut[ii * 72 + dq] = make_uint4(uo[0], uo[1], uo[2], uo[3]);
        *(uint4*)&qvt[ii * 72 + dq] = make_uint4(vo[0], vo[1], vo[2], vo[3]);
    }

    const unsigned aQU = sptr(qut) + (a_row * 72 + a_col) * 2;
    const unsigned aQV = sptr(qvt) + (a_row * 72 + a_col) * 2;
    const unsigned aKB4 = sptr(kbuf) + ((w * 16 + (g2 >> 1) * 8 + lr) * 72 + (g2 & 1) * 8) * 2;
    constexpr unsigned KBB = KB_E * 2;
    const int rlo = 992 - i0;
    const int srow = tid >> 1;                 // K/P staging: 128 rows, 2 thr/row
    const int sseg = (tid & 1) * 4;

    auto ldgP = [&](int ch, uint4* r) {
        int rr = rlo + ch * 128 + srow; if (rr > 2046) rr = 2046; if (rr < 0) rr = 0;
        const bf16* src = pbase + (size_t)rr * 64;
        #pragma unroll
        for (int it = 0; it < 4; it++) r[it] = *(const uint4*)(src + (sseg + it) * 8);
    };
    auto ldgK = [&](int ch, uint4* r) {
        const bf16* src = kbase + (size_t)(ch * 128 + srow) * 64;
        #pragma unroll
        for (int it = 0; it < 4; it++) r[it] = *(const uint4*)(src + (sseg + it) * 8);
    };
    auto stsK = [&](int buf, const uint4* r) {
        #pragma unroll
        for (int it = 0; it < 4; it++)
            *(uint4*)&kbuf[buf * KB_E + srow * 72 + (sseg + it) * 8] = r[it];
    };

    // ======== Phase B1: pos scores (9 chunks of 128), depth-2 pipeline ========
    {
        uint4 rA[4], rB[4];
        ldgP(0, rA); ldgP(1, rB);
        __syncthreads();                       // publish qut/qvt; kbuf free
        stsK(0, rA);
        unsigned af[2][4][4];
        #pragma unroll
        for (int ks = 0; ks < 4; ks++) {
            ldsm_x4(af[0][ks], aQV + ks * 32);
            ldsm_x4(af[1][ks], aQV + 16 * 144 + ks * 32);
        }
        auto comp = [&](int ch, unsigned off) {
            float4 cacc[2][2];
            #pragma unroll
            for (int mt = 0; mt < 2; mt++)
                #pragma unroll
                for (int nt = 0; nt < 2; nt++) cacc[mt][nt] = make_float4(0.f,0.f,0.f,0.f);
            #pragma unroll
            for (int ks = 0; ks < 4; ks++) {
                unsigned bb[4];
                ldsm_x4(bb, aKB4 + off + ks * 32);
                mma16(cacc[0][0], af[0][ks][0], af[0][ks][1], af[0][ks][2], af[0][ks][3], bb[0], bb[1]);
                mma16(cacc[1][0], af[1][ks][0], af[1][ks][1], af[1][ks][2], af[1][ks][3], bb[0], bb[1]);
                mma16(cacc[0][1], af[0][ks][0], af[0][ks][1], af[0][ks][2], af[0][ks][3], bb[2], bb[3]);
                mma16(cacc[1][1], af[1][ks][0], af[1][ks][1], af[1][ks][2], af[1][ks][3], bb[2], bb[3]);
            }
            if (ch == 0 || ch == 8) {
                #pragma unroll
                for (int mt = 0; mt < 2; mt++) {
                    #pragma unroll
                    for (int nt = 0; nt < 2; nt++) {
                        float4 c = cacc[mt][nt];
                        int ii = mt * 16 + gid;
                        int rr = ch * 128 + w * 16 + nt * 8 + tig * 2;
                        int jx = rr + ii - 31;
                        if (jx >= 0 && jx < 1024)         sc[ii * SCH + jx]     = __float2bfloat16(c.x);
                        if (jx + 1 >= 0 && jx + 1 < 1024) sc[ii * SCH + jx + 1] = __float2bfloat16(c.y);
                        int jz = jx + 8, i2 = ii + 8;
                        if (jz >= 0 && jz < 1024)         sc[i2 * SCH + jz]     = __float2bfloat16(c.z);
                        if (jz + 1 >= 0 && jz + 1 < 1024) sc[i2 * SCH + jz + 1] = __float2bfloat16(c.w);
                    }
                }
            } else {
                #pragma unroll
                for (int mt = 0; mt < 2; mt++) {
                    #pragma unroll
                    for (int nt = 0; nt < 2; nt++) {
                        float4 c = cacc[mt][nt];
                        int ii = mt * 16 + gid;
                        int jx = ch * 128 + w * 16 + nt * 8 + tig * 2 + ii - 31;
                        sc[ii * SCH + jx]           = __float2bfloat16(c.x);
                        sc[ii * SCH + jx + 1]       = __float2bfloat16(c.y);
                        sc[(ii + 8) * SCH + jx + 8] = __float2bfloat16(c.z);
                        sc[(ii + 8) * SCH + jx + 9] = __float2bfloat16(c.w);
                    }
                }
            }
        };
        #pragma unroll 1
        for (int c = 0; c < 8; c += 2) {
            ldgP(c + 2, rA);
            __syncthreads();
            stsK(1, rB);
            comp(c, 0u);
            if (c < 6) ldgP(c + 3, rB);
            __syncthreads();
            stsK(0, rA);
            comp(c + 1, KBB);
        }
        __syncthreads();
        comp(8, 0u);
    }

    // ======== Phase B2: content scores (8 chunks of 128), depth-2, bf16 RMW ========
    {
        uint4 rA[4], rB[4];
        ldgK(0, rA); ldgK(1, rB);
        __syncthreads();
        stsK(0, rA);
        unsigned af[2][4][4];
        #pragma unroll
        for (int ks = 0; ks < 4; ks++) {
            ldsm_x4(af[0][ks], aQU + ks * 32);
            ldsm_x4(af[1][ks], aQU + 16 * 144 + ks * 32);
        }
        auto comp = [&](int ch, unsigned off) {
            float4 cacc[2][2];
            #pragma unroll
            for (int mt = 0; mt < 2; mt++)
                #pragma unroll
                for (int nt = 0; nt < 2; nt++) cacc[mt][nt] = make_float4(0.f,0.f,0.f,0.f);
            #pragma unroll
            for (int ks = 0; ks < 4; ks++) {
                unsigned bb[4];
                ldsm_x4(bb, aKB4 + off + ks * 32);
                mma16(cacc[0][0], af[0][ks][0], af[0][ks][1], af[0][ks][2], af[0][ks][3], bb[0], bb[1]);
                mma16(cacc[1][0], af[1][ks][0], af[1][ks][1], af[1][ks][2], af[1][ks][3], bb[0], bb[1]);
                mma16(cacc[0][1], af[0][ks][0], af[0][ks][1], af[0][ks][2], af[0][ks][3], bb[2], bb[3]);
                mma16(cacc[1][1], af[1][ks][0], af[1][ks][1], af[1][ks][2], af[1][ks][3], bb[2], bb[3]);
            }
            #pragma unroll
            for (int mt = 0; mt < 2; mt++) {
                #pragma unroll
                for (int nt = 0; nt < 2; nt++) {
                    float4 c = cacc[mt][nt];
                    int ii = mt * 16 + gid;
                    int col = ch * 128 + w * 16 + nt * 8 + tig * 2;
                    unsigned* p0 = (unsigned*)&sc[ii * SCH + col];
                    unsigned u0 = *p0;
                    *p0 = pack_bf2(bf_lo(u0) + c.x, bf_hi(u0) + c.y);
                    unsigned* p1 = (unsigned*)&sc[(ii + 8) * SCH + col];
                    unsigned u1 = *p1;
                    *p1 = pack_bf2(bf_lo(u1) + c.z, bf_hi(u1) + c.w);
                }
            }
        };
        #pragma unroll 1
        for (int c = 0; c < 8; c += 2) {
            if (c < 6) ldgK(c + 2, rA);
            __syncthreads();
            stsK(1, rB);
            comp(c, 0u);
            if (c < 5) ldgK(c + 3, rB);
            __syncthreads();
            if (c < 6) stsK(0, rA);
            comp(c + 1, KBB);
        }
    }
    __syncthreads();

    // ======== Phase C: softmax (scale 1/8 inside exp), 4 rows per warp ========
    #pragma unroll
    for (int rr = 0; rr < 4; rr++) {
        int row = w * 4 + rr;
        bf16* rp = sc + row * SCH;
        unsigned u[16];
        float f[32];
        #pragma unroll
        for (int g = 0; g < 4; g++) {
            uint4 q4 = *(const uint4*)(rp + g * 256 + l * 8);
            u[g*4+0] = q4.x; u[g*4+1] = q4.y; u[g*4+2] = q4.z; u[g*4+3] = q4.w;
        }
        float mx = -1e30f;
        #pragma unroll
        for (int e = 0; e < 16; e++) {
            f[2*e]   = bf_lo(u[e]);
            f[2*e+1] = bf_hi(u[e]);
            mx = fmaxf(mx, fmaxf(f[2*e], f[2*e+1]));
        }
        #pragma unroll
        for (int o = 16; o; o >>= 1) mx = fmaxf(mx, __shfl_xor_sync(0xffffffffu, mx, o));
        float sum = 0.f;
        #pragma unroll
        for (int e = 0; e < 32; e++) {
            f[e] = __expf((f[e] - mx) * 0.125f);
            sum += f[e];
        }
        #pragma unroll
        for (int o = 16; o; o >>= 1) sum += __shfl_xor_sync(0xffffffffu, sum, o);
        float inv = 1.0f / sum;
        #pragma unroll
        for (int g = 0; g < 4; g++) {
            uint4 q4;
            q4.x = pack_bf2(f[g*8+0] * inv, f[g*8+1] * inv);
            q4.y = pack_bf2(f[g*8+2] * inv, f[g*8+3] * inv);
            q4.z = pack_bf2(f[g*8+4] * inv, f[g*8+5] * inv);
            q4.w = pack_bf2(f[g*8+6] * inv, f[g*8+7] * inv);
            *(uint4*)(rp + g * 256 + l * 8) = q4;
        }
    }

    // ======== Phase D: O = attn @ V (8 chunks of 128 keys), depth-2, 8-way k-split ========
    const int vrow = tid >> 2;                 // V staging: 64 rows, 4 thr/row
    const int vseg = (tid & 3) * 4;
    const unsigned aVT4 = sptr(kbuf) + (((g2 >> 1) * 8 + lr) * 136 + w * 16 + (g2 & 1) * 8) * 2;
    auto ldgV = [&](int ch, uint4* r) {
        const bf16* src = vbase + (size_t)vrow * 1024 + ch * 128;
        #pragma unroll
        for (int it = 0; it < 4; it++) r[it] = *(const uint4*)(src + (vseg + it) * 8);
    };
    auto stsV = [&](int buf, const uint4* r) {
        #pragma unroll
        for (int it = 0; it < 4; it++)
            *(uint4*)&kbuf[buf * KB_E + vrow * 136 + (vseg + it) * 8] = r[it];
    };

    float4 oacc[2][8];
    #pragma unroll
    for (int mt = 0; mt < 2; mt++)
        #pragma unroll
        for (int nt = 0; nt < 8; nt++) oacc[mt][nt] = make_float4(0.f,0.f,0.f,0.f);

    auto compD = [&](int ch, unsigned off) {
        unsigned a0[4], a1[4];
        ldsm_x4(a0, sptr(sc) + (a_row * SCH + ch * 128 + w * 16 + a_col) * 2);
        ldsm_x4(a1, sptr(sc) + ((16 + a_row) * SCH + ch * 128 + w * 16 + a_col) * 2);
        #pragma unroll
        for (int ntp = 0; ntp < 4; ntp++) {
            unsigned bb[4];
            ldsm_x4(bb, aVT4 + off + ntp * (16 * 272));
            mma16(oacc[0][2*ntp],   a0[0], a0[1], a0[2], a0[3], bb[0], bb[1]);
            mma16(oacc[1][2*ntp],   a1[0], a1[1], a1[2], a1[3], bb[0], bb[1]);
            mma16(oacc[0][2*ntp+1], a0[0], a0[1], a0[2], a0[3], bb[2], bb[3]);
            mma16(oacc[1][2*ntp+1], a1[0], a1[1], a1[2], a1[3], bb[2], bb[3]);
        }
    };
    {
        uint4 rA[4], rB[4];
        ldgV(0, rA); ldgV(1, rB);
        __syncthreads();                       // publish softmax sc; kbuf free
        stsV(0, rA);
        #pragma unroll 1
        for (int c = 0; c < 8; c += 2) {
            if (c < 6) ldgV(c + 2, rA);
            __syncthreads();
            stsV(1, rB);
            compD(c, 0u);
            if (c < 5) ldgV(c + 3, rB);
            __syncthreads();
            if (c < 6) stsV(0, rA);
            compD(c + 1, KBB);
        }
    }

    // per-warp partials -> fp32 overlay over sc (probs dead), then cross-warp reduce
    __syncthreads();
    float* ovl = (float*)sc;
    {
        float* pb = ovl + w * 2176;
        #pragma unroll
        for (int mt = 0; mt < 2; mt++) {
            #pragma unroll
            for (int nt = 0; nt < 8; nt++) {
                float4 c = oacc[mt][nt];
                int r = mt * 16 + gid;
                int cc = nt * 8 + tig * 2;
                pb[r * 68 + cc]           = c.x;
                pb[r * 68 + cc + 1]       = c.y;
                pb[(r + 8) * 68 + cc]     = c.z;
                pb[(r + 8) * 68 + cc + 1] = c.w;
            }
        }
    }
    __syncthreads();
    #pragma unroll
    for (int rep = 0; rep < 2; rep++) {
        int e = tid + rep * 256;
        int row = e >> 4, d4 = (e & 15) * 4;
        float4 s = make_float4(0.f, 0.f, 0.f, 0.f);
        #pragma unroll
        for (int ww = 0; ww < 8; ww++) {
            float4 p4 = *(const float4*)&ovl[ww * 2176 + row * 68 + d4];
            s.x += p4.x; s.y += p4.y; s.z += p4.z; s.w += p4.w;
        }
        *(uint2*)(ao + (size_t)(b * 1024 + i0 + row) * 512 + h * 64 + d4)
            = make_uint2(pack_bf2(s.x, s.y), pack_bf2(s.z, s.w));
    }
}

// ============================ launch ============================
extern "C" void kernel_launch(void* const* d_in, const int* in_sizes, int n_in,
                              void* d_out, int out_size)
{
    const float* x       = (const float*)d_in[0];
    const float* pos_emb = (const float*)d_in[1];
    const float* ln_w    = (const float*)d_in[2];
    const float* ln_b    = (const float*)d_in[3];
    const float* Wq      = (const float*)d_in[4];
    const float* bq      = (const float*)d_in[5];
    const float* Wk      = (const float*)d_in[6];
    const float* bk      = (const float*)d_in[7];
    const float* Wv      = (const float*)d_in[8];
    const float* bv      = (const float*)d_in[9];
    const float* Wo      = (const float*)d_in[10];
    const float* bo      = (const float*)d_in[11];
    const float* Wp      = (const float*)d_in[12];
    const float* pbu     = (const float*)d_in[13];
    const float* pbv     = (const float*)d_in[14];
    float* out = (float*)d_out;

    bf16 *hp, *qp, *kp, *vp, *pp, *aop;
    bf16 *wqp, *wkp, *wvp, *wop, *wpp, *pep;
    cudaGetSymbolAddress((void**)&hp,  g_h);
    cudaGetSymbolAddress((void**)&qp,  g_q);
    cudaGetSymbolAddress((void**)&kp,  g_k);
    cudaGetSymbolAddress((void**)&vp,  g_v);
    cudaGetSymbolAddress((void**)&pp,  g_p);
    cudaGetSymbolAddress((void**)&aop, g_ao);
    cudaGetSymbolAddress((void**)&wqp, g_wq);
    cudaGetSymbolAddress((void**)&wkp, g_wk);
    cudaGetSymbolAddress((void**)&wvp, g_wv);
    cudaGetSymbolAddress((void**)&wop, g_wo);
    cudaGetSymbolAddress((void**)&wpp, g_wp);
    cudaGetSymbolAddress((void**)&pep, g_pe);

    cudaFuncSetAttribute(attn_kernel, cudaFuncAttributeMaxDynamicSharedMemorySize, ASM_B);
    cudaFuncSetAttribute(gemm_kernel, cudaFuncAttributeMaxDynamicSharedMemorySize, GSM_B);
    cudaFuncSetAttribute(qkv_kernel,  cudaFuncAttributeMaxDynamicSharedMemorySize, GSM_B);

    wconv_kernel<<<dim3(128, 5), 256>>>(Wq, Wk, Wv, Wo, Wp, wqp, wkp, wvp, wop, wpp);
    peconv_kernel<<<512, 256>>>(pos_emb, pep, CP * CD / 8);
    ln_kernel<<<MTOK, 128>>>(x, ln_w, ln_b, hp);

    qkv_kernel<<<dim3(4, 64, 3), 256, GSM_B>>>(hp, wqp, wkp, wvp, bq, bk, bv, qp, kp, vp);
    gemm_kernel<<<dim3(4, 16), 256, GSM_B>>>(pep, CP, wpp, nullptr, nullptr, pp, 3);

    attn_kernel<<<CB * CH * (CS / 32), 256, ASM_B>>>(pbu, pbv, aop);

    gemm_kernel<<<dim3(4, 64), 256, GSM_B>>>(aop, MTOK, wop, bo, x, out, 4);
}

// round 16
// speedup vs baseline: 1.5357x; 1.0456x over previous
#include <cuda_runtime.h>
#include <cuda_bf16.h>

// ConformerAttention: B=8, S=1024, D=512, H=8, hd=64, P=2047
// rel_shift identity: shifted[i,j] = raw[i, j + (S-1) - i] -> p row r = 1023 + j - i.
// 32-row q tiles: rlo = 992 - i0, j = rr + ii - 31.

#define CB 8
#define CS 1024
#define CD 512
#define CH 8
#define CHD 64
#define CP 2047
#define MTOK (CB*CS)   // 8192

typedef __nv_bfloat16 bf16;

__device__ __forceinline__ unsigned pack_bf2(float lo, float hi) {
    unsigned r; asm("cvt.rn.bf16x2.f32 %0, %1, %2;" : "=r"(r) : "f"(hi), "f"(lo)); return r;
}
__device__ __forceinline__ float bf_lo(unsigned u) { return __uint_as_float(u << 16); }
__device__ __forceinline__ float bf_hi(unsigned u) { return __uint_as_float(u & 0xFFFF0000u); }

__device__ __forceinline__ void mma16(float4& c, unsigned a0, unsigned a1, unsigned a2, unsigned a3,
                                      unsigned b0, unsigned b1) {
    asm volatile(
        "mma.sync.aligned.m16n8k16.row.col.f32.bf16.bf16.f32 "
        "{%0,%1,%2,%3}, {%4,%5,%6,%7}, {%8,%9}, {%0,%1,%2,%3};"
        : "+f"(c.x), "+f"(c.y), "+f"(c.z), "+f"(c.w)
        : "r"(a0), "r"(a1), "r"(a2), "r"(a3), "r"(b0), "r"(b1));
}
__device__ __forceinline__ unsigned sptr(const void* p) {
    return (unsigned)__cvta_generic_to_shared(p);
}
__device__ __forceinline__ void ldsm_x4(unsigned* r, unsigned addr) {
    asm volatile("ldmatrix.sync.aligned.m8n8.x4.shared.b16 {%0,%1,%2,%3}, [%4];"
        : "=r"(r[0]), "=r"(r[1]), "=r"(r[2]), "=r"(r[3]) : "r"(addr));
}

// -------- scratch (allocation-free: device globals) --------
__device__ bf16 g_h [MTOK*CD];
__device__ bf16 g_q [CB*CH*CS*CHD];      // [bh][S][hd]
__device__ bf16 g_k [CB*CH*CS*CHD];      // [bh][S][hd]
__device__ bf16 g_v [CB*CH*CS*CHD];      // [bh][hd][S]  (pre-transposed, mode 5)
__device__ bf16 g_p [CH*CP*CHD];         // [H][P][hd]
__device__ bf16 g_ao[MTOK*CD];           // [B,S,D]
__device__ bf16 g_wq[CD*CD], g_wk[CD*CD], g_wv[CD*CD], g_wo[CD*CD], g_wp[CD*CD];
__device__ bf16 g_pe[CP*CD];             // pos_emb bf16

// ============================ fp32 -> bf16 conversions ============================
__global__ void __launch_bounds__(256) wconv_kernel(
    const float* __restrict__ w0, const float* __restrict__ w1, const float* __restrict__ w2,
    const float* __restrict__ w3, const float* __restrict__ w4,
    bf16* __restrict__ d0, bf16* __restrict__ d1, bf16* __restrict__ d2,
    bf16* __restrict__ d3, bf16* __restrict__ d4)
{
    int y = blockIdx.y;
    const float* s = (y == 0) ? w0 : (y == 1) ? w1 : (y == 2) ? w2 : (y == 3) ? w3 : w4;
    bf16* d        = (y == 0) ? d0 : (y == 1) ? d1 : (y == 2) ? d2 : (y == 3) ? d3 : d4;
    int i = blockIdx.x * 256 + threadIdx.x;
    float4 f0 = *((const float4*)s + i * 2);
    float4 f1 = *((const float4*)s + i * 2 + 1);
    *(uint4*)(d + i * 8) = make_uint4(pack_bf2(f0.x, f0.y), pack_bf2(f0.z, f0.w),
                                      pack_bf2(f1.x, f1.y), pack_bf2(f1.z, f1.w));
}
__global__ void __launch_bounds__(256) peconv_kernel(const float* __restrict__ s, bf16* __restrict__ d, int n8)
{
    int i = blockIdx.x * 256 + threadIdx.x;
    if (i >= n8) return;
    float4 f0 = *((const float4*)s + i * 2);
    float4 f1 = *((const float4*)s + i * 2 + 1);
    *(uint4*)(d + i * 8) = make_uint4(pack_bf2(f0.x, f0.y), pack_bf2(f0.z, f0.w),
                                      pack_bf2(f1.x, f1.y), pack_bf2(f1.z, f1.w));
}

// ============================ LayerNorm (fp32 in -> bf16 out) ============================
__global__ void __launch_bounds__(128) ln_kernel(const float* __restrict__ x,
    const float* __restrict__ w, const float* __restrict__ b, bf16* __restrict__ out)
{
    int row = blockIdx.x;
    int t = threadIdx.x;
    const float* xr = x + (size_t)row * CD;
    float4 v = *(const float4*)(xr + t * 4);
    float s = v.x + v.y + v.z + v.w;
    #pragma unroll
    for (int o = 16; o; o >>= 1) s += __shfl_xor_sync(0xffffffffu, s, o);
    __shared__ float ws1[4], ws2[4];
    if ((t & 31) == 0) ws1[t >> 5] = s;
    __syncthreads();
    float mean = (ws1[0] + ws1[1] + ws1[2] + ws1[3]) * (1.0f / 512.0f);
    float dx = v.x - mean, dy = v.y - mean, dz = v.z - mean, dw = v.w - mean;
    float q = dx*dx + dy*dy + dz*dz + dw*dw;
    #pragma unroll
    for (int o = 16; o; o >>= 1) q += __shfl_xor_sync(0xffffffffu, q, o);
    if ((t & 31) == 0) ws2[t >> 5] = q;
    __syncthreads();
    float var = (ws2[0] + ws2[1] + ws2[2] + ws2[3]) * (1.0f / 512.0f);
    float rstd = rsqrtf(var + 1e-5f);
    float4 wv = *(const float4*)(w + t * 4);
    float4 bv = *(const float4*)(b + t * 4);
    float ox = dx * rstd * wv.x + bv.x;
    float oy = dy * rstd * wv.y + bv.y;
    float oz = dz * rstd * wv.z + bv.z;
    float ow = dw * rstd * wv.w + bv.w;
    *(uint2*)(out + (size_t)row * CD + t * 4) = make_uint2(pack_bf2(ox, oy), pack_bf2(oz, ow));
}

// ============================ GEMM core (bf16 mma, x4 B-frags, staged epilogue) ============================
constexpr int GKC  = 128 * 72;             // elems per stage buffer
constexpr int GSM_B = 4 * GKC * 2;         // 73,728 bytes dynamic

__device__ __forceinline__ void gemm_core(
    const bf16* __restrict__ A, int M,
    const bf16* __restrict__ W,
    const float* __restrict__ bias,
    const float* __restrict__ resid,
    void* __restrict__ outp, int mode,
    bf16* As, bf16* Ws)
{
    const int tid = threadIdx.x;
    const int l = tid & 31, wid = tid >> 5;
    const int wm = wid >> 1, wn = wid & 1;
    const int m0 = blockIdx.y * 128, n0 = blockIdx.x * 128;
    const int gid = l >> 2, tig = l & 3;
    const int lr = l & 7;
    const int g2 = l >> 3;
    const int a_row = ((l >> 3) & 1) * 8 + lr;
    const int a_col = (l >> 4) * 8;

    float4 cacc[2][8];
    #pragma unroll
    for (int mt = 0; mt < 2; mt++)
        #pragma unroll
        for (int nt = 0; nt < 8; nt++) cacc[mt][nt] = make_float4(0.f, 0.f, 0.f, 0.f);

    const unsigned aA = sptr(As) + ((wm * 32 + a_row) * 72 + a_col) * 2;
    const unsigned aB4 = sptr(Ws) + ((wn * 64 + (g2 >> 1) * 8 + lr) * 72 + (g2 & 1) * 8) * 2;

    uint4 ra[4], rw[4];
    auto ldg = [&](int k0) {
        #pragma unroll
        for (int it = 0; it < 4; it++) {
            int idx = tid + it * 256;
            int row = idx >> 3, seg = idx & 7;
            int kk = k0 + seg * 8;
            int am = m0 + row; if (am >= M) am = M - 1;
            ra[it] = *(const uint4*)(A + (size_t)am * 512 + kk);
            rw[it] = *(const uint4*)(W + (size_t)(n0 + row) * 512 + kk);
        }
    };
    auto sts = [&](int buf) {
        #pragma unroll
        for (int it = 0; it < 4; it++) {
            int idx = tid + it * 256;
            int row = idx >> 3, seg = idx & 7;
            *(uint4*)&As[buf * GKC + row * 72 + seg * 8] = ra[it];
            *(uint4*)&Ws[buf * GKC + row * 72 + seg * 8] = rw[it];
        }
    };

    ldg(0);
    sts(0);
    for (int c = 0; c < 8; c++) {
        if (c < 7) ldg((c + 1) * 64);
        __syncthreads();
        unsigned off = (unsigned)(c & 1) * (GKC * 2);
        #pragma unroll
        for (int ks = 0; ks < 4; ks++) {
            unsigned a0[4], a1[4];
            ldsm_x4(a0, aA + off + ks * 32);
            ldsm_x4(a1, aA + off + 16 * 144 + ks * 32);
            #pragma unroll
            for (int ntp = 0; ntp < 4; ntp++) {
                unsigned bb[4];
                ldsm_x4(bb, aB4 + off + ntp * (16 * 144) + ks * 32);
                mma16(cacc[0][2*ntp],   a0[0], a0[1], a0[2], a0[3], bb[0], bb[1]);
                mma16(cacc[1][2*ntp],   a1[0], a1[1], a1[2], a1[3], bb[0], bb[1]);
                mma16(cacc[0][2*ntp+1], a0[0], a0[1], a0[2], a0[3], bb[2], bb[3]);
                mma16(cacc[1][2*ntp+1], a1[0], a1[1], a1[2], a1[3], bb[2], bb[3]);
            }
        }
        if (c < 7) sts((c + 1) & 1);
    }

    if (mode == 4) {
        #pragma unroll
        for (int mt = 0; mt < 2; mt++) {
            #pragma unroll
            for (int nt = 0; nt < 8; nt++) {
                float4 c = cacc[mt][nt];
                int r0 = m0 + wm * 32 + mt * 16 + gid;
                int c0 = n0 + wn * 64 + nt * 8 + tig * 2;
                float vals[4] = {c.x, c.y, c.z, c.w};
                #pragma unroll
                for (int e = 0; e < 4; e++) {
                    int m = r0 + (e >= 2 ? 8 : 0);
                    int n = c0 + (e & 1);
                    size_t idx = (size_t)m * 512 + n;
                    ((float*)outp)[idx] = vals[e] + bias[n] + resid[idx];
                }
            }
        }
        return;
    }

    // staged coalesced epilogue for modes 0/3/5
    __syncthreads();
    bf16* Cst = As;                                  // [128][136]
    if (mode == 5) {
        #pragma unroll
        for (int mt = 0; mt < 2; mt++) {
            #pragma unroll
            for (int nt = 0; nt < 8; nt++) {
                float4 c = cacc[mt][nt];
                int r0 = wm * 32 + mt * 16 + gid;
                int c0 = wn * 64 + nt * 8 + tig * 2;
                float bx = bias[n0 + c0], by = bias[n0 + c0 + 1];
                Cst[c0 * 136 + r0]           = __float2bfloat16(c.x + bx);
                Cst[(c0 + 1) * 136 + r0]     = __float2bfloat16(c.y + by);
                Cst[c0 * 136 + r0 + 8]       = __float2bfloat16(c.z + bx);
                Cst[(c0 + 1) * 136 + r0 + 8] = __float2bfloat16(c.w + by);
            }
        }
    } else {
        #pragma unroll
        for (int mt = 0; mt < 2; mt++) {
            #pragma unroll
            for (int nt = 0; nt < 8; nt++) {
                float4 c = cacc[mt][nt];
                int r0 = wm * 32 + mt * 16 + gid;
                int c0 = wn * 64 + nt * 8 + tig * 2;
                float bx = (mode == 3) ? 0.f : bias[n0 + c0];
                float by = (mode == 3) ? 0.f : bias[n0 + c0 + 1];
                *(unsigned*)&Cst[r0 * 136 + c0]       = pack_bf2(c.x + bx, c.y + by);
                *(unsigned*)&Cst[(r0 + 8) * 136 + c0] = pack_bf2(c.z + bx, c.w + by);
            }
        }
    }
    __syncthreads();
    {
        int rl = tid & 127, hf = tid >> 7;
        const uint4* s4 = (const uint4*)(Cst + rl * 136 + hf * 64);
        if (mode == 5) {
            int n = n0 + rl, d = n & 63, hh = n >> 6;
            int mb = m0 + hf * 64;
            bf16* dst = (bf16*)outp + ((size_t)((mb >> 10) * CH + hh) << 16)
                        + (size_t)d * 1024 + (mb & 1023);
            #pragma unroll
            for (int i = 0; i < 8; i++) ((uint4*)dst)[i] = s4[i];
        } else if (mode == 0) {
            int m = m0 + rl;
            int hh = (n0 >> 6) + hf;
            bf16* dst = (bf16*)outp + ((size_t)((m >> 10) * CH + hh) << 16)
                        + (size_t)(m & 1023) * 64;
            #pragma unroll
            for (int i = 0; i < 8; i++) ((uint4*)dst)[i] = s4[i];
        } else {  // mode 3
            int m = m0 + rl;
            if (m < M) {
                int hh = (n0 >> 6) + hf;
                bf16* dst = (bf16*)outp + (size_t)hh * (CP * 64) + (size_t)m * 64;
                #pragma unroll
                for (int i = 0; i < 8; i++) ((uint4*)dst)[i] = s4[i];
            }
        }
    }
}

__global__ void __launch_bounds__(256, 2) gemm_kernel(
    const bf16* __restrict__ Ap, int M,
    const bf16* __restrict__ W, const float* __restrict__ bias,
    const float* __restrict__ resid, void* __restrict__ outp, int mode)
{
    extern __shared__ bf16 gsm[];
    gemm_core(Ap, M, W, bias, resid, outp, mode, gsm, gsm + 2 * GKC);
}

// fused QKV + pos projection, SINGLE gemm_core call site (one inlined instance)
__global__ void __launch_bounds__(256, 2) qkv_kernel(
    const bf16* __restrict__ A,
    const bf16* __restrict__ Wq, const bf16* __restrict__ Wk, const bf16* __restrict__ Wv,
    const float* __restrict__ bq, const float* __restrict__ bk, const float* __restrict__ bv,
    bf16* __restrict__ q, bf16* __restrict__ k, bf16* __restrict__ v,
    const bf16* __restrict__ pe, const bf16* __restrict__ Wp, bf16* __restrict__ p)
{
    extern __shared__ bf16 gsm[];
    int z = blockIdx.z;
    if (z == 3 && blockIdx.y >= 16) return;
    const bf16* Aop   = (z == 3) ? pe : A;
    int M             = (z == 3) ? CP : MTOK;
    const bf16* W     = (z == 0) ? Wq : (z == 1) ? Wk : (z == 2) ? Wv : Wp;
    const float* bias = (z == 0) ? bq : (z == 1) ? bk : bv;   // unused for mode 3
    bf16* o           = (z == 0) ? q  : (z == 1) ? k  : (z == 2) ? v : p;
    int mode          = (z == 3) ? 3 : (z == 2) ? 5 : 0;
    gemm_core(Aop, M, W, bias, nullptr, o, mode, gsm, gsm + 2 * GKC);
}

// ============================ Fused attention (bf16 scores, depth-2 B pipelines, depth-1 D) ============================
constexpr int SCH    = 1080;               // bf16 score stride (135*16B rows: ldsm conflict-free)
constexpr int SC_E   = 32 * SCH;           // 34560
constexpr int QT_E   = 32 * 72;            // 2304 each
constexpr int KB_E   = 128 * 72;           // 9216 per buffer (Vt 64*136=8704 fits)
constexpr int ASM_B  = (SC_E + 2 * QT_E + 2 * KB_E) * 2;   // 115,200 bytes -> 2 CTAs/SM

__global__ void __launch_bounds__(256, 2) attn_kernel(const float* __restrict__ bu,
    const float* __restrict__ bvp, bf16* __restrict__ ao)
{
    extern __shared__ bf16 smb[];
    bf16* sc   = smb;                  // [32][1080] bf16 scores/probs
    bf16* qut  = smb + SC_E;           // [32][72]
    bf16* qvt  = qut + QT_E;           // [32][72]
    bf16* kbuf = qvt + QT_E;           // 2 x [128][72] K/P chunks; Vt 2 x [64][136]

    const int tid = threadIdx.x;
    const int w = tid >> 5, l = tid & 31;
    const int gid = l >> 2, tig = l & 3;
    const int lr = l & 7;
    const int g2 = l >> 3;
    const int a_row = ((l >> 3) & 1) * 8 + lr;
    const int a_col = (l >> 4) * 8;
    const int qt = blockIdx.x & 31;
    const int bh = blockIdx.x >> 5;
    const int h  = bh & 7, b = bh >> 3;
    const int i0 = qt * 32;
    const bf16* qbase = g_q + (size_t)bh * (CS * CHD);
    const bf16* kbase = g_k + (size_t)bh * (CS * CHD);
    const bf16* vbase = g_v + (size_t)bh * (CS * CHD);   // [64][1024]
    const bf16* pbase = g_p + (size_t)h  * (CP * CHD);

    // ---- Phase A: q tile [32][72] bf16, both bias variants ----
    {
        int ii = tid >> 3, dq = (tid & 7) * 8;
        uint4 qw = *(const uint4*)(qbase + (size_t)(i0 + ii) * 64 + dq);
        unsigned wsv[4] = {qw.x, qw.y, qw.z, qw.w};
        unsigned uo[4], vo[4];
        #pragma unroll
        for (int j = 0; j < 4; j++) {
            float fx = bf_lo(wsv[j]), fy = bf_hi(wsv[j]);
            int d = dq + 2 * j;
            uo[j] = pack_bf2(fx + bu [h*64+d], fy + bu [h*64+d+1]);
            vo[j] = pack_bf2(fx + bvp[h*64+d], fy + bvp[h*64+d+1]);
        }
        *(uint4*)&qut[ii * 72 + dq] = make_uint4(uo[0], uo[1], uo[2], uo[3]);
        *(uint4*)&qvt[ii * 72 + dq] = make_uint4(vo[0], vo[1], vo[2], vo[3]);
    }

    const unsigned aQU = sptr(qut) + (a_row * 72 + a_col) * 2;
    const unsigned aQV = sptr(qvt) + (a_row * 72 + a_col) * 2;
    const unsigned aKB4 = sptr(kbuf) + ((w * 16 + (g2 >> 1) * 8 + lr) * 72 + (g2 & 1) * 8) * 2;
    constexpr unsigned KBB = KB_E * 2;
    const int rlo = 992 - i0;
    const int srow = tid >> 1;                 // K/P staging: 128 rows, 2 thr/row
    const int sseg = (tid & 1) * 4;

    auto ldgP = [&](int ch, uint4* r) {
        int rr = rlo + ch * 128 + srow; if (rr > 2046) rr = 2046; if (rr < 0) rr = 0;
        const bf16* src = pbase + (size_t)rr * 64;
        #pragma unroll
        for (int it = 0; it < 4; it++) r[it] = *(const uint4*)(src + (sseg + it) * 8);
    };
    auto ldgK = [&](int ch, uint4* r) {
        const bf16* src = kbase + (size_t)(ch * 128 + srow) * 64;
        #pragma unroll
        for (int it = 0; it < 4; it++) r[it] = *(const uint4*)(src + (sseg + it) * 8);
    };
    auto stsK = [&](int buf, const uint4* r) {
        #pragma unroll
        for (int it = 0; it < 4; it++)
            *(uint4*)&kbuf[buf * KB_E + srow * 72 + (sseg + it) * 8] = r[it];
    };

    // ======== Phase B1: pos scores (9 chunks of 128), depth-2 pipeline ========
    {
        uint4 rA[4], rB[4];
        ldgP(0, rA); ldgP(1, rB);
        __syncthreads();                       // publish qut/qvt; kbuf free
        stsK(0, rA);
        unsigned af[2][4][4];
        #pragma unroll
        for (int ks = 0; ks < 4; ks++) {
            ldsm_x4(af[0][ks], aQV + ks * 32);
            ldsm_x4(af[1][ks], aQV + 16 * 144 + ks * 32);
        }
        auto comp = [&](int ch, unsigned off) {
            float4 cacc[2][2];
            #pragma unroll
            for (int mt = 0; mt < 2; mt++)
                #pragma unroll
                for (int nt = 0; nt < 2; nt++) cacc[mt][nt] = make_float4(0.f,0.f,0.f,0.f);
            #pragma unroll
            for (int ks = 0; ks < 4; ks++) {
                unsigned bb[4];
                ldsm_x4(bb, aKB4 + off + ks * 32);
                mma16(cacc[0][0], af[0][ks][0], af[0][ks][1], af[0][ks][2], af[0][ks][3], bb[0], bb[1]);
                mma16(cacc[1][0], af[1][ks][0], af[1][ks][1], af[1][ks][2], af[1][ks][3], bb[0], bb[1]);
                mma16(cacc[0][1], af[0][ks][0], af[0][ks][1], af[0][ks][2], af[0][ks][3], bb[2], bb[3]);
                mma16(cacc[1][1], af[1][ks][0], af[1][ks][1], af[1][ks][2], af[1][ks][3], bb[2], bb[3]);
            }
            if (ch == 0 || ch == 8) {
                #pragma unroll
                for (int mt = 0; mt < 2; mt++) {
                    #pragma unroll
                    for (int nt = 0; nt < 2; nt++) {
                        float4 c = cacc[mt][nt];
                        int ii = mt * 16 + gid;
                        int rr = ch * 128 + w * 16 + nt * 8 + tig * 2;
                        int jx = rr + ii - 31;
                        if (jx >= 0 && jx < 1024)         sc[ii * SCH + jx]     = __float2bfloat16(c.x);
                        if (jx + 1 >= 0 && jx + 1 < 1024) sc[ii * SCH + jx + 1] = __float2bfloat16(c.y);
                        int jz = jx + 8, i2 = ii + 8;
                        if (jz >= 0 && jz < 1024)         sc[i2 * SCH + jz]     = __float2bfloat16(c.z);
                        if (jz + 1 >= 0 && jz + 1 < 1024) sc[i2 * SCH + jz + 1] = __float2bfloat16(c.w);
                    }
                }
            } else {
                #pragma unroll
                for (int mt = 0; mt < 2; mt++) {
                    #pragma unroll
                    for (int nt = 0; nt < 2; nt++) {
                        float4 c = cacc[mt][nt];
                        int ii = mt * 16 + gid;
                        int jx = ch * 128 + w * 16 + nt * 8 + tig * 2 + ii - 31;
                        sc[ii * SCH + jx]           = __float2bfloat16(c.x);
                        sc[ii * SCH + jx + 1]       = __float2bfloat16(c.y);
                        sc[(ii + 8) * SCH + jx + 8] = __float2bfloat16(c.z);
                        sc[(ii + 8) * SCH + jx + 9] = __float2bfloat16(c.w);
                    }
                }
            }
        };
        #pragma unroll 1
        for (int c = 0; c < 8; c += 2) {
            ldgP(c + 2, rA);
            __syncthreads();
            stsK(1, rB);
            comp(c, 0u);
            if (c < 6) ldgP(c + 3, rB);
            __syncthreads();
            stsK(0, rA);
            comp(c + 1, KBB);
        }
        __syncthreads();
        comp(8, 0u);
    }

    // ======== Phase B2: content scores (8 chunks of 128), depth-2, bf16 RMW ========
    {
        uint4 rA[4], rB[4];
        ldgK(0, rA); ldgK(1, rB);
        __syncthreads();
        stsK(0, rA);
        unsigned af[2][4][4];
        #pragma unroll
        for (int ks = 0; ks < 4; ks++) {
            ldsm_x4(af[0][ks], aQU + ks * 32);
            ldsm_x4(af[1][ks], aQU + 16 * 144 + ks * 32);
        }
        auto comp = [&](int ch, unsigned off) {
            float4 cacc[2][2];
            #pragma unroll
            for (int mt = 0; mt < 2; mt++)
                #pragma unroll
                for (int nt = 0; nt < 2; nt++) cacc[mt][nt] = make_float4(0.f,0.f,0.f,0.f);
            #pragma unroll
            for (int ks = 0; ks < 4; ks++) {
                unsigned bb[4];
                ldsm_x4(bb, aKB4 + off + ks * 32);
                mma16(cacc[0][0], af[0][ks][0], af[0][ks][1], af[0][ks][2], af[0][ks][3], bb[0], bb[1]);
                mma16(cacc[1][0], af[1][ks][0], af[1][ks][1], af[1][ks][2], af[1][ks][3], bb[0], bb[1]);
                mma16(cacc[0][1], af[0][ks][0], af[0][ks][1], af[0][ks][2], af[0][ks][3], bb[2], bb[3]);
                mma16(cacc[1][1], af[1][ks][0], af[1][ks][1], af[1][ks][2], af[1][ks][3], bb[2], bb[3]);
            }
            #pragma unroll
            for (int mt = 0; mt < 2; mt++) {
                #pragma unroll
                for (int nt = 0; nt < 2; nt++) {
                    float4 c = cacc[mt][nt];
                    int ii = mt * 16 + gid;
                    int col = ch * 128 + w * 16 + nt * 8 + tig * 2;
                    unsigned* p0 = (unsigned*)&sc[ii * SCH + col];
                    unsigned u0 = *p0;
                    *p0 = pack_bf2(bf_lo(u0) + c.x, bf_hi(u0) + c.y);
                    unsigned* p1 = (unsigned*)&sc[(ii + 8) * SCH + col];
                    unsigned u1 = *p1;
                    *p1 = pack_bf2(bf_lo(u1) + c.z, bf_hi(u1) + c.w);
                }
            }
        };
        #pragma unroll 1
        for (int c = 0; c < 8; c += 2) {
            if (c < 6) ldgK(c + 2, rA);
            __syncthreads();
            stsK(1, rB);
            comp(c, 0u);
            if (c < 5) ldgK(c + 3, rB);
            __syncthreads();
            if (c < 6) stsK(0, rA);
            comp(c + 1, KBB);
        }
    }
    __syncthreads();

    // ======== Phase C: softmax (scale 1/8 inside exp), 4 rows per warp ========
    #pragma unroll
    for (int rr = 0; rr < 4; rr++) {
        int row = w * 4 + rr;
        bf16* rp = sc + row * SCH;
        unsigned u[16];
        float f[32];
        #pragma unroll
        for (int g = 0; g < 4; g++) {
            uint4 q4 = *(const uint4*)(rp + g * 256 + l * 8);
            u[g*4+0] = q4.x; u[g*4+1] = q4.y; u[g*4+2] = q4.z; u[g*4+3] = q4.w;
        }
        float mx = -1e30f;
        #pragma unroll
        for (int e = 0; e < 16; e++) {
            f[2*e]   = bf_lo(u[e]);
            f[2*e+1] = bf_hi(u[e]);
            mx = fmaxf(mx, fmaxf(f[2*e], f[2*e+1]));
        }
        #pragma unroll
        for (int o = 16; o; o >>= 1) mx = fmaxf(mx, __shfl_xor_sync(0xffffffffu, mx, o));
        float sum = 0.f;
        #pragma unroll
        for (int e = 0; e < 32; e++) {
            f[e] = __expf((f[e] - mx) * 0.125f);
            sum += f[e];
        }
        #pragma unroll
        for (int o = 16; o; o >>= 1) sum += __shfl_xor_sync(0xffffffffu, sum, o);
        float inv = 1.0f / sum;
        #pragma unroll
        for (int g = 0; g < 4; g++) {
            uint4 q4;
            q4.x = pack_bf2(f[g*8+0] * inv, f[g*8+1] * inv);
            q4.y = pack_bf2(f[g*8+2] * inv, f[g*8+3] * inv);
            q4.z = pack_bf2(f[g*8+4] * inv, f[g*8+5] * inv);
            q4.w = pack_bf2(f[g*8+6] * inv, f[g*8+7] * inv);
            *(uint4*)(rp + g * 256 + l * 8) = q4;
        }
    }

    // ======== Phase D: O = attn @ V (8 chunks of 128 keys), depth-1, 8-way k-split ========
    const int vrow = tid >> 2;                 // V staging: 64 rows, 4 thr/row
    const int vseg = (tid & 3) * 4;
    const unsigned aVT4 = sptr(kbuf) + (((g2 >> 1) * 8 + lr) * 136 + w * 16 + (g2 & 1) * 8) * 2;
    uint4 rk[4];
    auto ldgV = [&](int ch) {
        const bf16* src = vbase + (size_t)vrow * 1024 + ch * 128;
        #pragma unroll
        for (int it = 0; it < 4; it++) rk[it] = *(const uint4*)(src + (vseg + it) * 8);
    };
    auto stsV = [&](int buf) {
        #pragma unroll
        for (int it = 0; it < 4; it++)
            *(uint4*)&kbuf[buf * KB_E + vrow * 136 + (vseg + it) * 8] = rk[it];
    };

    float4 oacc[2][8];
    #pragma unroll
    for (int mt = 0; mt < 2; mt++)
        #pragma unroll
        for (int nt = 0; nt < 8; nt++) oacc[mt][nt] = make_float4(0.f,0.f,0.f,0.f);

    ldgV(0);
    __syncthreads();                           // softmax sc writes published; kbuf free
    stsV(0);
    #pragma unroll 1
    for (int ch = 0; ch < 8; ch++) {
        if (ch < 7) ldgV(ch + 1);
        __syncthreads();
        unsigned off = (unsigned)(ch & 1) * KBB;
        unsigned a0[4], a1[4];
        ldsm_x4(a0, sptr(sc) + (a_row * SCH + ch * 128 + w * 16 + a_col) * 2);
        ldsm_x4(a1, sptr(sc) + ((16 + a_row) * SCH + ch * 128 + w * 16 + a_col) * 2);
        #pragma unroll
        for (int ntp = 0; ntp < 4; ntp++) {
            unsigned bb[4];
            ldsm_x4(bb, aVT4 + off + ntp * (16 * 272));
            mma16(oacc[0][2*ntp],   a0[0], a0[1], a0[2], a0[3], bb[0], bb[1]);
            mma16(oacc[1][2*ntp],   a1[0], a1[1], a1[2], a1[3], bb[0], bb[1]);
            mma16(oacc[0][2*ntp+1], a0[0], a0[1], a0[2], a0[3], bb[2], bb[3]);
            mma16(oacc[1][2*ntp+1], a1[0], a1[1], a1[2], a1[3], bb[2], bb[3]);
        }
        if (ch < 7) stsV((ch + 1) & 1);
    }

    // per-warp partials -> fp32 overlay over sc (probs dead), then cross-warp reduce
    __syncthreads();
    float* ovl = (float*)sc;
    {
        float* pb = ovl + w * 2176;
        #pragma unroll
        for (int mt = 0; mt < 2; mt++) {
            #pragma unroll
            for (int nt = 0; nt < 8; nt++) {
                float4 c = oacc[mt][nt];
                int r = mt * 16 + gid;
                int cc = nt * 8 + tig * 2;
                pb[r * 68 + cc]           = c.x;
                pb[r * 68 + cc + 1]       = c.y;
                pb[(r + 8) * 68 + cc]     = c.z;
                pb[(r + 8) * 68 + cc + 1] = c.w;
            }
        }
    }
    __syncthreads();
    #pragma unroll
    for (int rep = 0; rep < 2; rep++) {
        int e = tid + rep * 256;
        int row = e >> 4, d4 = (e & 15) * 4;
        float4 s = make_float4(0.f, 0.f, 0.f, 0.f);
        #pragma unroll
        for (int ww = 0; ww < 8; ww++) {
            float4 p4 = *(const float4*)&ovl[ww * 2176 + row * 68 + d4];
            s.x += p4.x; s.y += p4.y; s.z += p4.z; s.w += p4.w;
        }
        *(uint2*)(ao + (size_t)(b * 1024 + i0 + row) * 512 + h * 64 + d4)
            = make_uint2(pack_bf2(s.x, s.y), pack_bf2(s.z, s.w));
    }
}

// ============================ launch ============================
extern "C" void kernel_launch(void* const* d_in, const int* in_sizes, int n_in,
                              void* d_out, int out_size)
{
    const float* x       = (const float*)d_in[0];
    const float* pos_emb = (const float*)d_in[1];
    const float* ln_w    = (const float*)d_in[2];
    const float* ln_b    = (const float*)d_in[3];
    const float* Wq      = (const float*)d_in[4];
    const float* bq      = (const float*)d_in[5];
    const float* Wk      = (const float*)d_in[6];
    const float* bk      = (const float*)d_in[7];
    const float* Wv      = (const float*)d_in[8];
    const float* bv      = (const float*)d_in[9];
    const float* Wo      = (const float*)d_in[10];
    const float* bo      = (const float*)d_in[11];
    const float* Wp      = (const float*)d_in[12];
    const float* pbu     = (const float*)d_in[13];
    const float* pbv     = (const float*)d_in[14];
    float* out = (float*)d_out;

    bf16 *hp, *qp, *kp, *vp, *pp, *aop;
    bf16 *wqp, *wkp, *wvp, *wop, *wpp, *pep;
    cudaGetSymbolAddress((void**)&hp,  g_h);
    cudaGetSymbolAddress((void**)&qp,  g_q);
    cudaGetSymbolAddress((void**)&kp,  g_k);
    cudaGetSymbolAddress((void**)&vp,  g_v);
    cudaGetSymbolAddress((void**)&pp,  g_p);
    cudaGetSymbolAddress((void**)&aop, g_ao);
    cudaGetSymbolAddress((void**)&wqp, g_wq);
    cudaGetSymbolAddress((void**)&wkp, g_wk);
    cudaGetSymbolAddress((void**)&wvp, g_wv);
    cudaGetSymbolAddress((void**)&wop, g_wo);
    cudaGetSymbolAddress((void**)&wpp, g_wp);
    cudaGetSymbolAddress((void**)&pep, g_pe);

    cudaFuncSetAttribute(attn_kernel, cudaFuncAttributeMaxDynamicSharedMemorySize, ASM_B);
    cudaFuncSetAttribute(gemm_kernel, cudaFuncAttributeMaxDynamicSharedMemorySize, GSM_B);
    cudaFuncSetAttribute(qkv_kernel,  cudaFuncAttributeMaxDynamicSharedMemorySize, GSM_B);

    wconv_kernel<<<dim3(128, 5), 256>>>(Wq, Wk, Wv, Wo, Wp, wqp, wkp, wvp, wop, wpp);
    peconv_kernel<<<512, 256>>>(pos_emb, pep, CP * CD / 8);
    ln_kernel<<<MTOK, 128>>>(x, ln_w, ln_b, hp);

    qkv_kernel<<<dim3(4, 64, 4), 256, GSM_B>>>(hp, wqp, wkp, wvp, bq, bk, bv,
                                               qp, kp, vp, pep, wpp, pp);

    attn_kernel<<<CB * CH * (CS / 32), 256, ASM_B>>>(pbu, pbv, aop);

    gemm_kernel<<<dim3(4, 64), 256, GSM_B>>>(aop, MTOK, wop, bo, x, out, 4);
}